// round 3
// baseline (speedup 1.0000x reference)
#include <cuda_runtime.h>

// Problem constants
constexpr int C_DIM  = 512;
constexpr int NHEADS = 8;
constexpr int HD     = 64;
constexpr int NB     = 8;
constexpr int NSEQ   = 1024;
constexpr int M_TOT  = NB * NSEQ;     // 8192
constexpr int KVN    = 2 * C_DIM;     // 1024
constexpr float SCALE = 0.125f;       // 64^-0.5

// Scratch for kv1 / kv2: [2][B*N, 1024]  (64 MB static device memory)
__device__ float g_kv[2][(size_t)M_TOT * KVN];

// ---------------------------------------------------------------------------
// Kernel 1: kv = x @ W   (two GEMMs, blockIdx.z = branch)
// 128x128 tile, BK=8, 256 threads, 8x8 register blocking, register prefetch.
// ---------------------------------------------------------------------------
__global__ __launch_bounds__(256) void kv_gemm(const float* __restrict__ x1,
                                               const float* __restrict__ x2,
                                               const float* __restrict__ w1,
                                               const float* __restrict__ w2) {
    const int br = blockIdx.z;
    const float* __restrict__ X = br ? x2 : x1;
    const float* __restrict__ W = br ? w2 : w1;
    float* __restrict__ Cout = g_kv[br];

    __shared__ float As[8][132];   // transposed A tile: As[k][m]
    __shared__ float Bs[8][128];

    const int t  = threadIdx.x;
    const int tx = t & 15;
    const int ty = t >> 4;
    const int m0 = blockIdx.y * 128;
    const int n0 = blockIdx.x * 128;

    const int arow = t >> 1;
    const int ac4  = (t & 1) * 4;
    const int brow = t >> 5;
    const int bc4  = (t & 31) * 4;

    float acc[8][8] = {};

    float4 av = *(const float4*)&X[(size_t)(m0 + arow) * C_DIM + ac4];
    float4 bv = *(const float4*)&W[(size_t)brow * KVN + n0 + bc4];

    for (int k0 = 0; k0 < C_DIM; k0 += 8) {
        __syncthreads();
        As[ac4 + 0][arow] = av.x;
        As[ac4 + 1][arow] = av.y;
        As[ac4 + 2][arow] = av.z;
        As[ac4 + 3][arow] = av.w;
        *(float4*)&Bs[brow][bc4] = bv;
        __syncthreads();

        if (k0 + 8 < C_DIM) {   // prefetch next K-slab while computing
            av = *(const float4*)&X[(size_t)(m0 + arow) * C_DIM + k0 + 8 + ac4];
            bv = *(const float4*)&W[(size_t)(k0 + 8 + brow) * KVN + n0 + bc4];
        }

        #pragma unroll
        for (int kk = 0; kk < 8; kk++) {
            float a[8], b[8];
            const float4 a0 = *(const float4*)&As[kk][ty * 8 + 0];
            const float4 a1 = *(const float4*)&As[kk][ty * 8 + 4];
            a[0] = a0.x; a[1] = a0.y; a[2] = a0.z; a[3] = a0.w;
            a[4] = a1.x; a[5] = a1.y; a[6] = a1.z; a[7] = a1.w;
            const float4 b0 = *(const float4*)&Bs[kk][tx * 8 + 0];
            const float4 b1 = *(const float4*)&Bs[kk][tx * 8 + 4];
            b[0] = b0.x; b[1] = b0.y; b[2] = b0.z; b[3] = b0.w;
            b[4] = b1.x; b[5] = b1.y; b[6] = b1.z; b[7] = b1.w;
            #pragma unroll
            for (int i = 0; i < 8; i++)
                #pragma unroll
                for (int j = 0; j < 8; j++)
                    acc[i][j] = fmaf(a[i], b[j], acc[i][j]);
        }
    }

    #pragma unroll
    for (int i = 0; i < 8; i++) {
        const size_t row = (size_t)(m0 + ty * 8 + i) * KVN + n0 + tx * 8;
        float4 v0 = {acc[i][0], acc[i][1], acc[i][2], acc[i][3]};
        float4 v1 = {acc[i][4], acc[i][5], acc[i][6], acc[i][7]};
        *(float4*)&Cout[row + 0] = v0;
        *(float4*)&Cout[row + 4] = v1;
    }
}

// ---------------------------------------------------------------------------
// Kernel 2: fused cross attention, 8x8 blocking in BOTH gemm stages.
// CTA = (q-tile of 256 rows, b*h, branch); 16 kv tiles of 64 rows.
// 256 threads as (ty 0..31 row-groups) x (tx 0..7 col-groups); 8x8 per thread.
// smem (dynamic 144KB): qT[64][256] | U = kT[64][64] / S[256][64] swizzled | v[64][64]
// ---------------------------------------------------------------------------
__global__ __launch_bounds__(256) void attn_kernel(const float* __restrict__ x1,
                                                   const float* __restrict__ x2,
                                                   float* __restrict__ out) {
    extern __shared__ float sm[];
    float* __restrict__ qT = sm;            // qT[d][i] = sm[d*256 + i]
    float* __restrict__ U  = sm + 16384;    // kT: [d*64 + j] ; S: row*64 + swizzled chunk
    float* __restrict__ Vs = sm + 32768;    // v[m][c] = Vs[m*64 + c]

    const int br = blockIdx.z;
    const int bh = blockIdx.y;
    const int bb = bh >> 3;
    const int hh = bh & 7;
    const int qt = blockIdx.x;

    const float* __restrict__ q_g = (br ? x2 : x1)
        + (size_t)bb * NSEQ * C_DIM + (size_t)qt * 256 * C_DIM + hh * HD;
    const float* __restrict__ k_g = g_kv[1 - br] + (size_t)bb * NSEQ * KVN + hh * HD;
    const float* __restrict__ v_g = g_kv[br] + (size_t)bb * NSEQ * KVN + C_DIM + hh * HD;
    float* __restrict__ o_g = out + (size_t)br * NB * NSEQ * C_DIM
        + (size_t)bb * NSEQ * C_DIM + (size_t)qt * 256 * C_DIM + hh * HD;

    const int t  = threadIdx.x;
    const int tx = t & 7;     // col-group (8 cols each)
    const int ty = t >> 3;    // row-group (8 rows each), 0..31
    const int rb = ty & 7;    // swizzle key for this thread's rows

    // ---- load q tile transposed: qT[d][i] ----
    #pragma unroll
    for (int l = 0; l < 16; l++) {
        const int slot = t + l * 256;           // 0..4095 float4 slots
        const int i  = slot & 255;
        const int d0 = (slot >> 8) << 2;
        const float4 q4 = *(const float4*)&q_g[(size_t)i * C_DIM + d0];
        qT[(d0 + 0) * 256 + i] = q4.x;
        qT[(d0 + 1) * 256 + i] = q4.y;
        qT[(d0 + 2) * 256 + i] = q4.z;
        qT[(d0 + 3) * 256 + i] = q4.w;
    }

    float o_acc[8][8] = {};
    float4 kreg[4], vreg[4];

    // prefetch tile 0
    #pragma unroll
    for (int l = 0; l < 4; l++) {
        const int slot = t + l * 256;
        const int kj = slot & 63,  kd0 = (slot >> 6) << 2;
        const int vm = slot >> 4,  vc0 = (slot & 15) << 2;
        kreg[l] = *(const float4*)&k_g[(size_t)kj * KVN + kd0];
        vreg[l] = *(const float4*)&v_g[(size_t)vm * KVN + vc0];
    }

    for (int mt = 0; mt < 16; mt++) {
        __syncthreads();   // prev stage2 reads of S (aliased with kT) and v done; q STS done on mt=0

        // STS prefetched k (transposed) and v
        #pragma unroll
        for (int l = 0; l < 4; l++) {
            const int slot = t + l * 256;
            const int kj = slot & 63,  kd0 = (slot >> 6) << 2;
            const int vm = slot >> 4,  vc0 = (slot & 15) << 2;
            U[(kd0 + 0) * 64 + kj] = kreg[l].x;
            U[(kd0 + 1) * 64 + kj] = kreg[l].y;
            U[(kd0 + 2) * 64 + kj] = kreg[l].z;
            U[(kd0 + 3) * 64 + kj] = kreg[l].w;
            *(float4*)&Vs[vm * 64 + vc0] = vreg[l];
        }
        __syncthreads();

        if (mt + 1 < 16) {   // prefetch next tile while stage1 computes
            #pragma unroll
            for (int l = 0; l < 4; l++) {
                const int slot = t + l * 256;
                const int kj = slot & 63,  kd0 = (slot >> 6) << 2;
                const int vm = slot >> 4,  vc0 = (slot & 15) << 2;
                kreg[l] = *(const float4*)&k_g[(size_t)((mt + 1) * 64 + kj) * KVN + kd0];
                vreg[l] = *(const float4*)&v_g[(size_t)((mt + 1) * 64 + vm) * KVN + vc0];
            }
        }

        // ---- stage 1: S = q . k^T  (8x8 per thread) ----
        float s_acc[8][8] = {};
        #pragma unroll
        for (int d = 0; d < 64; d++) {
            float a[8], b[8];
            const float4 a0 = *(const float4*)&qT[d * 256 + ty * 8 + 0];
            const float4 a1 = *(const float4*)&qT[d * 256 + ty * 8 + 4];
            a[0] = a0.x; a[1] = a0.y; a[2] = a0.z; a[3] = a0.w;
            a[4] = a1.x; a[5] = a1.y; a[6] = a1.z; a[7] = a1.w;
            const float4 b0 = *(const float4*)&U[d * 64 + tx * 8 + 0];
            const float4 b1 = *(const float4*)&U[d * 64 + tx * 8 + 4];
            b[0] = b0.x; b[1] = b0.y; b[2] = b0.z; b[3] = b0.w;
            b[4] = b1.x; b[5] = b1.y; b[6] = b1.z; b[7] = b1.w;
            #pragma unroll
            for (int i = 0; i < 8; i++)
                #pragma unroll
                for (int j = 0; j < 8; j++)
                    s_acc[i][j] = fmaf(a[i], b[j], s_acc[i][j]);
        }
        __syncthreads();   // all kT reads done before aliasing U with S

        // relu + scale, store S with XOR-swizzled column chunks
        #pragma unroll
        for (int a = 0; a < 8; a++) {
            const int row = ty * 8 + a;
            #pragma unroll
            for (int h = 0; h < 2; h++) {
                const int phys = ((tx * 2 + h) ^ rb) << 2;
                float4 sv;
                sv.x = fmaxf(s_acc[a][h * 4 + 0], 0.0f) * SCALE;
                sv.y = fmaxf(s_acc[a][h * 4 + 1], 0.0f) * SCALE;
                sv.z = fmaxf(s_acc[a][h * 4 + 2], 0.0f) * SCALE;
                sv.w = fmaxf(s_acc[a][h * 4 + 3], 0.0f) * SCALE;
                *(float4*)&U[row * 64 + phys] = sv;
            }
        }
        __syncthreads();

        // ---- stage 2: O += S . v  (8x8 per thread, same (ty,tx) mapping) ----
        #pragma unroll
        for (int c4 = 0; c4 < 16; c4++) {        // m-chunk of 4
            const int phys = (c4 ^ rb) << 2;
            float4 s4[8];
            #pragma unroll
            for (int i = 0; i < 8; i++)
                s4[i] = *(const float4*)&U[(ty * 8 + i) * 64 + phys];
            #pragma unroll
            for (int mm = 0; mm < 4; mm++) {
                const int m = c4 * 4 + mm;
                const float4 v0 = *(const float4*)&Vs[m * 64 + tx * 8 + 0];
                const float4 v1 = *(const float4*)&Vs[m * 64 + tx * 8 + 4];
                #pragma unroll
                for (int i = 0; i < 8; i++) {
                    const float s = (mm == 0) ? s4[i].x : (mm == 1) ? s4[i].y
                                  : (mm == 2) ? s4[i].z : s4[i].w;
                    o_acc[i][0] = fmaf(s, v0.x, o_acc[i][0]);
                    o_acc[i][1] = fmaf(s, v0.y, o_acc[i][1]);
                    o_acc[i][2] = fmaf(s, v0.z, o_acc[i][2]);
                    o_acc[i][3] = fmaf(s, v0.w, o_acc[i][3]);
                    o_acc[i][4] = fmaf(s, v1.x, o_acc[i][4]);
                    o_acc[i][5] = fmaf(s, v1.y, o_acc[i][5]);
                    o_acc[i][6] = fmaf(s, v1.z, o_acc[i][6]);
                    o_acc[i][7] = fmaf(s, v1.w, o_acc[i][7]);
                }
            }
        }
    }

    // ---- epilogue ----
    #pragma unroll
    for (int a = 0; a < 8; a++) {
        const size_t row = (size_t)(ty * 8 + a) * C_DIM + tx * 8;
        float4 ov0 = {o_acc[a][0], o_acc[a][1], o_acc[a][2], o_acc[a][3]};
        float4 ov1 = {o_acc[a][4], o_acc[a][5], o_acc[a][6], o_acc[a][7]};
        *(float4*)&o_g[row + 0] = ov0;
        *(float4*)&o_g[row + 4] = ov1;
    }
}

// ---------------------------------------------------------------------------
constexpr int ATTN_SMEM = (16384 + 16384 + 4096) * 4;   // 147456 B

extern "C" void kernel_launch(void* const* d_in, const int* in_sizes, int n_in,
                              void* d_out, int out_size) {
    const float* x1 = (const float*)d_in[0];
    const float* x2 = (const float*)d_in[1];
    const float* w1 = (const float*)d_in[2];
    const float* w2 = (const float*)d_in[3];
    float* out = (float*)d_out;

    (void)cudaFuncSetAttribute(attn_kernel,
                               cudaFuncAttributeMaxDynamicSharedMemorySize, ATTN_SMEM);

    dim3 g1(KVN / 128, M_TOT / 128, 2);     // (8, 64, 2)
    kv_gemm<<<g1, 256>>>(x1, x2, w1, w2);

    dim3 g2(NSEQ / 256, NB * NHEADS, 2);    // (4, 64, 2)
    attn_kernel<<<g2, 256, ATTN_SMEM>>>(x1, x2, out);
}

// round 4
// speedup vs baseline: 3.0141x; 3.0141x over previous
#include <cuda_runtime.h>
#include <cuda_bf16.h>
#include <cstdint>

// Problem constants
constexpr int C_DIM  = 512;
constexpr int NHEADS = 8;
constexpr int HD     = 64;
constexpr int NB     = 8;
constexpr int NSEQ   = 1024;
constexpr int M_TOT  = NB * NSEQ;     // 8192
constexpr int KVN    = 2 * C_DIM;     // 1024
constexpr float SCALE = 0.125f;       // 64^-0.5

// kv scratch as bf16 split planes: hi + lo (error-compensated bf16x2 representation)
__device__ __nv_bfloat16 g_kvh[2][(size_t)M_TOT * KVN];
__device__ __nv_bfloat16 g_kvl[2][(size_t)M_TOT * KVN];

// ---------------------------------------------------------------------------
// helpers
// ---------------------------------------------------------------------------
__device__ __forceinline__ uint32_t smem_u32(const void* p) {
    return (uint32_t)__cvta_generic_to_shared(p);
}
__device__ __forceinline__ void ldsm_x4(uint32_t* r, uint32_t a) {
    asm volatile("ldmatrix.sync.aligned.m8n8.x4.shared.b16 {%0,%1,%2,%3}, [%4];"
                 : "=r"(r[0]), "=r"(r[1]), "=r"(r[2]), "=r"(r[3]) : "r"(a));
}
__device__ __forceinline__ void ldsm_x2t(uint32_t* r, uint32_t a) {
    asm volatile("ldmatrix.sync.aligned.m8n8.x2.trans.shared.b16 {%0,%1}, [%2];"
                 : "=r"(r[0]), "=r"(r[1]) : "r"(a));
}
__device__ __forceinline__ void mma16816(float* c, const uint32_t* a, const uint32_t* b) {
    asm volatile("mma.sync.aligned.m16n8k16.row.col.f32.bf16.bf16.f32 "
                 "{%0,%1,%2,%3}, {%4,%5,%6,%7}, {%8,%9}, {%0,%1,%2,%3};"
                 : "+f"(c[0]), "+f"(c[1]), "+f"(c[2]), "+f"(c[3])
                 : "r"(a[0]), "r"(a[1]), "r"(a[2]), "r"(a[3]), "r"(b[0]), "r"(b[1]));
}
// split fp32 pair into packed bf16x2 hi and lo (residual) words
__device__ __forceinline__ void split2(float x0, float x1, uint32_t& hi, uint32_t& lo) {
    __nv_bfloat16 h0 = __float2bfloat16_rn(x0);
    __nv_bfloat16 h1 = __float2bfloat16_rn(x1);
    __nv_bfloat162 hp; hp.x = h0; hp.y = h1;
    __nv_bfloat162 lp;
    lp.x = __float2bfloat16_rn(x0 - __bfloat162float(h0));
    lp.y = __float2bfloat16_rn(x1 - __bfloat162float(h1));
    hi = *reinterpret_cast<uint32_t*>(&hp);
    lo = *reinterpret_cast<uint32_t*>(&lp);
}

// ---------------------------------------------------------------------------
// Kernel 1: kv = x @ W  (fp32 FFMA GEMM, epilogue writes bf16 hi/lo planes)
// ---------------------------------------------------------------------------
__global__ __launch_bounds__(256) void kv_gemm(const float* __restrict__ x1,
                                               const float* __restrict__ x2,
                                               const float* __restrict__ w1,
                                               const float* __restrict__ w2) {
    const int br = blockIdx.z;
    const float* __restrict__ X = br ? x2 : x1;
    const float* __restrict__ W = br ? w2 : w1;
    __nv_bfloat16* __restrict__ Oh = g_kvh[br];
    __nv_bfloat16* __restrict__ Ol = g_kvl[br];

    __shared__ float As[8][132];
    __shared__ float Bs[8][128];

    const int t  = threadIdx.x;
    const int tx = t & 15;
    const int ty = t >> 4;
    const int m0 = blockIdx.y * 128;
    const int n0 = blockIdx.x * 128;

    const int arow = t >> 1;
    const int ac4  = (t & 1) * 4;
    const int brow = t >> 5;
    const int bc4  = (t & 31) * 4;

    float acc[8][8] = {};

    float4 av = *(const float4*)&X[(size_t)(m0 + arow) * C_DIM + ac4];
    float4 bv = *(const float4*)&W[(size_t)brow * KVN + n0 + bc4];

    for (int k0 = 0; k0 < C_DIM; k0 += 8) {
        __syncthreads();
        As[ac4 + 0][arow] = av.x;
        As[ac4 + 1][arow] = av.y;
        As[ac4 + 2][arow] = av.z;
        As[ac4 + 3][arow] = av.w;
        *(float4*)&Bs[brow][bc4] = bv;
        __syncthreads();

        if (k0 + 8 < C_DIM) {
            av = *(const float4*)&X[(size_t)(m0 + arow) * C_DIM + k0 + 8 + ac4];
            bv = *(const float4*)&W[(size_t)(k0 + 8 + brow) * KVN + n0 + bc4];
        }

        #pragma unroll
        for (int kk = 0; kk < 8; kk++) {
            float a[8], b[8];
            const float4 a0 = *(const float4*)&As[kk][ty * 8 + 0];
            const float4 a1 = *(const float4*)&As[kk][ty * 8 + 4];
            a[0] = a0.x; a[1] = a0.y; a[2] = a0.z; a[3] = a0.w;
            a[4] = a1.x; a[5] = a1.y; a[6] = a1.z; a[7] = a1.w;
            const float4 b0 = *(const float4*)&Bs[kk][tx * 8 + 0];
            const float4 b1 = *(const float4*)&Bs[kk][tx * 8 + 4];
            b[0] = b0.x; b[1] = b0.y; b[2] = b0.z; b[3] = b0.w;
            b[4] = b1.x; b[5] = b1.y; b[6] = b1.z; b[7] = b1.w;
            #pragma unroll
            for (int i = 0; i < 8; i++)
                #pragma unroll
                for (int j = 0; j < 8; j++)
                    acc[i][j] = fmaf(a[i], b[j], acc[i][j]);
        }
    }

    #pragma unroll
    for (int i = 0; i < 8; i++) {
        const size_t base = (size_t)(m0 + ty * 8 + i) * KVN + n0 + tx * 8;
        uint32_t hp[4], lp[4];
        #pragma unroll
        for (int jj = 0; jj < 4; jj++)
            split2(acc[i][2 * jj], acc[i][2 * jj + 1], hp[jj], lp[jj]);
        *(uint4*)&Oh[base] = *(uint4*)hp;
        *(uint4*)&Ol[base] = *(uint4*)lp;
    }
}

// ---------------------------------------------------------------------------
// Kernel 2: fused cross attention on tensor cores (mma.sync bf16, hi/lo split).
// CTA: 128 q rows x (b*h) x branch. 8 warps; warp w owns q rows [16w, 16w+16).
// kv processed in 8 tiles of 128 rows.
// smem (bf16, all tiles padded to row stride 88): QH QL KH KL VH VL.
// ---------------------------------------------------------------------------
constexpr int PAD = 88;                 // 176B stride: conflict-free ldmatrix, 16B aligned
constexpr int TILE_ELE = 128 * PAD;     // 11264 bf16 per plane
constexpr int ATTN_SMEM = 6 * TILE_ELE * 2;   // 135168 bytes

__global__ __launch_bounds__(256, 1) void attn_kernel(const float* __restrict__ x1,
                                                      const float* __restrict__ x2,
                                                      float* __restrict__ out) {
    extern __shared__ __nv_bfloat16 smb[];
    __nv_bfloat16* QH = smb;
    __nv_bfloat16* QL = smb + TILE_ELE;
    __nv_bfloat16* KH = smb + 2 * TILE_ELE;
    __nv_bfloat16* KL = smb + 3 * TILE_ELE;
    __nv_bfloat16* VH = smb + 4 * TILE_ELE;
    __nv_bfloat16* VL = smb + 5 * TILE_ELE;

    const int br = blockIdx.z;
    const int bh = blockIdx.y;
    const int bb = bh >> 3;
    const int hh = bh & 7;
    const int qt = blockIdx.x;

    const float* __restrict__ q_g = (br ? x2 : x1)
        + (size_t)bb * NSEQ * C_DIM + (size_t)qt * 128 * C_DIM + hh * HD;
    const __nv_bfloat16* __restrict__ KHg = g_kvh[1 - br];
    const __nv_bfloat16* __restrict__ KLg = g_kvl[1 - br];
    const __nv_bfloat16* __restrict__ VHg = g_kvh[br];
    const __nv_bfloat16* __restrict__ VLg = g_kvl[br];
    float* __restrict__ o_g = out + (size_t)br * NB * NSEQ * C_DIM
        + (size_t)bb * NSEQ * C_DIM + (size_t)qt * 128 * C_DIM + hh * HD;

    const int tid  = threadIdx.x;
    const int w    = tid >> 5;
    const int lane = tid & 31;
    const int g    = lane >> 2;     // group id (rows within fragment)
    const int tq   = lane & 3;      // thread-in-group (col pairs)

    // ---- load + split q tile (128 x 64 fp32 -> QH/QL) ----
    #pragma unroll
    for (int l = 0; l < 8; l++) {
        const int c   = tid + l * 256;          // 0..2047 float4 chunks
        const int row = c >> 4;
        const int c4  = (c & 15) * 4;
        const float4 q4 = *(const float4*)&q_g[(size_t)row * C_DIM + c4];
        uint32_t h0, l0, h1, l1;
        split2(q4.x, q4.y, h0, l0);
        split2(q4.z, q4.w, h1, l1);
        uint2 hv = {h0, h1}, lv = {l0, l1};
        *(uint2*)&QH[row * PAD + c4] = hv;
        *(uint2*)&QL[row * PAD + c4] = lv;
    }

    float oacc[8][4] = {};    // 8 d-tiles (n8) of output, C-fragment layout

    const size_t kv_row0 = (size_t)bb * NSEQ;
    const int kcol = hh * HD;
    const int vcol = C_DIM + hh * HD;

    // ldmatrix lane-address components (computed once)
    const int a_row_off = (lane & 7) + ((lane >> 3) & 1) * 8;   // for x4 A/B loads
    const int a_col_off = ((lane >> 4) & 1) * 8;
    const int v_row_off = lane & 15;                            // for x2 trans loads

    for (int mt = 0; mt < 8; mt++) {
        __syncthreads();   // previous iteration's fragment loads complete

        // ---- fill K/V tiles (bf16 hi/lo, straight row-major copies) ----
        const size_t rbase = kv_row0 + mt * 128;
        #pragma unroll
        for (int l = 0; l < 4; l++) {
            const int c  = tid + l * 256;       // 0..1023 chunks of 8 bf16
            const int m  = c >> 3;
            const int d8 = (c & 7) * 8;
            const size_t gidx = (rbase + m) * KVN;
            *(uint4*)&KH[m * PAD + d8] = *(const uint4*)&KHg[gidx + kcol + d8];
            *(uint4*)&KL[m * PAD + d8] = *(const uint4*)&KLg[gidx + kcol + d8];
            *(uint4*)&VH[m * PAD + d8] = *(const uint4*)&VHg[gidx + vcol + d8];
            *(uint4*)&VL[m * PAD + d8] = *(const uint4*)&VLg[gidx + vcol + d8];
        }
        __syncthreads();

        // ---- stage 1: S(16 x 128) = q . k^T, bf16x3 split ----
        uint32_t ah[16], al[16];
        #pragma unroll
        for (int ks = 0; ks < 4; ks++) {
            const int arow = w * 16 + a_row_off;
            const int acol = ks * 16 + a_col_off;
            ldsm_x4(&ah[ks * 4], smem_u32(&QH[arow * PAD + acol]));
            ldsm_x4(&al[ks * 4], smem_u32(&QL[arow * PAD + acol]));
        }

        float sacc[16][4];
        #pragma unroll
        for (int nt = 0; nt < 16; nt++)
            #pragma unroll
            for (int r = 0; r < 4; r++) sacc[nt][r] = 0.0f;

        #pragma unroll
        for (int nt = 0; nt < 16; nt++) {
            const int brow = nt * 8 + (lane & 7);
            const int bcol = ((lane >> 3) & 3) * 8;    // 0,8,16,24 across lane groups
            uint32_t bhf[8], blf[8];
            ldsm_x4(&bhf[0], smem_u32(&KH[brow * PAD + bcol]));
            ldsm_x4(&bhf[4], smem_u32(&KH[brow * PAD + 32 + bcol]));
            ldsm_x4(&blf[0], smem_u32(&KL[brow * PAD + bcol]));
            ldsm_x4(&blf[4], smem_u32(&KL[brow * PAD + 32 + bcol]));
            #pragma unroll
            for (int ks = 0; ks < 4; ks++) {
                mma16816(sacc[nt], &ah[ks * 4], &bhf[ks * 2]);   // hi*hi
                mma16816(sacc[nt], &ah[ks * 4], &blf[ks * 2]);   // hi*lo
                mma16816(sacc[nt], &al[ks * 4], &bhf[ks * 2]);   // lo*hi
            }
        }

        // ---- stage 2: O += relu(S*scale) . v ----
        #pragma unroll
        for (int j = 0; j < 8; j++) {            // kv k-steps of 16
            // convert S tiles 2j, 2j+1 (register-local: C-frag == A-frag layout)
            float r00 = fmaxf(sacc[2*j][0], 0.0f) * SCALE;
            float r01 = fmaxf(sacc[2*j][1], 0.0f) * SCALE;
            float r02 = fmaxf(sacc[2*j][2], 0.0f) * SCALE;
            float r03 = fmaxf(sacc[2*j][3], 0.0f) * SCALE;
            float r10 = fmaxf(sacc[2*j+1][0], 0.0f) * SCALE;
            float r11 = fmaxf(sacc[2*j+1][1], 0.0f) * SCALE;
            float r12 = fmaxf(sacc[2*j+1][2], 0.0f) * SCALE;
            float r13 = fmaxf(sacc[2*j+1][3], 0.0f) * SCALE;
            uint32_t sah[4], sal[4];
            split2(r00, r01, sah[0], sal[0]);
            split2(r02, r03, sah[1], sal[1]);
            split2(r10, r11, sah[2], sal[2]);
            split2(r12, r13, sah[3], sal[3]);

            const int vrow = j * 16 + v_row_off;
            #pragma unroll
            for (int nt2 = 0; nt2 < 8; nt2++) {
                uint32_t bvh[2], bvl[2];
                ldsm_x2t(bvh, smem_u32(&VH[vrow * PAD + nt2 * 8]));
                ldsm_x2t(bvl, smem_u32(&VL[vrow * PAD + nt2 * 8]));
                mma16816(oacc[nt2], sah, bvh);
                mma16816(oacc[nt2], sah, bvl);
                mma16816(oacc[nt2], sal, bvh);
            }
        }
    }

    // ---- epilogue: C-fragment scatter to out (fp32) ----
    #pragma unroll
    for (int nt2 = 0; nt2 < 8; nt2++) {
        float2 v0 = {oacc[nt2][0], oacc[nt2][1]};
        float2 v1 = {oacc[nt2][2], oacc[nt2][3]};
        *(float2*)&o_g[(size_t)(w * 16 + g) * C_DIM + nt2 * 8 + 2 * tq] = v0;
        *(float2*)&o_g[(size_t)(w * 16 + g + 8) * C_DIM + nt2 * 8 + 2 * tq] = v1;
    }
}

// ---------------------------------------------------------------------------
extern "C" void kernel_launch(void* const* d_in, const int* in_sizes, int n_in,
                              void* d_out, int out_size) {
    const float* x1 = (const float*)d_in[0];
    const float* x2 = (const float*)d_in[1];
    const float* w1 = (const float*)d_in[2];
    const float* w2 = (const float*)d_in[3];
    float* out = (float*)d_out;

    (void)cudaFuncSetAttribute(attn_kernel,
                               cudaFuncAttributeMaxDynamicSharedMemorySize, ATTN_SMEM);

    dim3 g1(KVN / 128, M_TOT / 128, 2);     // (8, 64, 2)
    kv_gemm<<<g1, 256>>>(x1, x2, w1, w2);

    dim3 g2(NSEQ / 128, NB * NHEADS, 2);    // (8, 64, 2)
    attn_kernel<<<g2, 256, ATTN_SMEM>>>(x1, x2, out);
}

// round 5
// speedup vs baseline: 4.2297x; 1.4033x over previous
#include <cuda_runtime.h>
#include <cuda_bf16.h>
#include <cstdint>

// Problem constants
constexpr int C_DIM  = 512;
constexpr int NHEADS = 8;
constexpr int HD     = 64;
constexpr int NB     = 8;
constexpr int NSEQ   = 1024;
constexpr int M_TOT  = NB * NSEQ;     // 8192
constexpr int KVN    = 2 * C_DIM;     // 1024
constexpr float SCALE = 0.125f;       // 64^-0.5

// kv scratch as bf16 split planes: hi + lo residual
__device__ __nv_bfloat16 g_kvh[2][(size_t)M_TOT * KVN];
__device__ __nv_bfloat16 g_kvl[2][(size_t)M_TOT * KVN];

// ---------------------------------------------------------------------------
// helpers
// ---------------------------------------------------------------------------
__device__ __forceinline__ uint32_t smem_u32(const void* p) {
    return (uint32_t)__cvta_generic_to_shared(p);
}
__device__ __forceinline__ void ldsm_x4(uint32_t* r, uint32_t a) {
    asm volatile("ldmatrix.sync.aligned.m8n8.x4.shared.b16 {%0,%1,%2,%3}, [%4];"
                 : "=r"(r[0]), "=r"(r[1]), "=r"(r[2]), "=r"(r[3]) : "r"(a));
}
__device__ __forceinline__ void ldsm_x4t(uint32_t* r, uint32_t a) {
    asm volatile("ldmatrix.sync.aligned.m8n8.x4.trans.shared.b16 {%0,%1,%2,%3}, [%4];"
                 : "=r"(r[0]), "=r"(r[1]), "=r"(r[2]), "=r"(r[3]) : "r"(a));
}
__device__ __forceinline__ void mma16816(float* c, const uint32_t* a, const uint32_t* b) {
    asm volatile("mma.sync.aligned.m16n8k16.row.col.f32.bf16.bf16.f32 "
                 "{%0,%1,%2,%3}, {%4,%5,%6,%7}, {%8,%9}, {%0,%1,%2,%3};"
                 : "+f"(c[0]), "+f"(c[1]), "+f"(c[2]), "+f"(c[3])
                 : "r"(a[0]), "r"(a[1]), "r"(a[2]), "r"(a[3]), "r"(b[0]), "r"(b[1]));
}
__device__ __forceinline__ void split2(float x0, float x1, uint32_t& hi, uint32_t& lo) {
    __nv_bfloat16 h0 = __float2bfloat16_rn(x0);
    __nv_bfloat16 h1 = __float2bfloat16_rn(x1);
    __nv_bfloat162 hp; hp.x = h0; hp.y = h1;
    __nv_bfloat162 lp;
    lp.x = __float2bfloat16_rn(x0 - __bfloat162float(h0));
    lp.y = __float2bfloat16_rn(x1 - __bfloat162float(h1));
    hi = *reinterpret_cast<uint32_t*>(&hp);
    lo = *reinterpret_cast<uint32_t*>(&lp);
}

// ---------------------------------------------------------------------------
// Kernel 1: kv = x @ W on tensor cores (bf16 hi/lo split, 3 products).
// 128x128 CTA tile, K-step 32. 8 warps: warp tile 64 (M) x 32 (N).
// smem: XH/XL [128][40], WH/WL [32][136], split on the fly from fp32.
// ---------------------------------------------------------------------------
constexpr int XPAD = 40;
constexpr int WPAD = 136;

__global__ __launch_bounds__(256, 1) void kv_gemm(const float* __restrict__ x1,
                                                  const float* __restrict__ x2,
                                                  const float* __restrict__ w1,
                                                  const float* __restrict__ w2) {
    const int br = blockIdx.z;
    const float* __restrict__ X = br ? x2 : x1;
    const float* __restrict__ W = br ? w2 : w1;
    __nv_bfloat16* __restrict__ Oh = g_kvh[br];
    __nv_bfloat16* __restrict__ Ol = g_kvl[br];

    __shared__ __nv_bfloat16 XH[128 * XPAD], XL[128 * XPAD];
    __shared__ __nv_bfloat16 WH[32 * WPAD],  WL[32 * WPAD];

    const int t    = threadIdx.x;
    const int w    = t >> 5;
    const int lane = t & 31;
    const int g    = lane >> 2;
    const int tq   = lane & 3;
    const int wm   = w >> 2;
    const int wn   = w & 3;
    const int m0   = blockIdx.y * 128;
    const int n0   = blockIdx.x * 128;

    const int a_row = wm * 64 + (lane & 7) + ((lane >> 3) & 1) * 8;
    const int a_col = ((lane >> 4) & 1) * 8;
    const int b_quad = lane >> 3;
    const int b_r    = lane & 7;

    float4 xa[4], wb[4];
    #pragma unroll
    for (int l = 0; l < 4; l++) {
        const int slot = t + l * 256;
        const int xr = slot >> 3, xc = (slot & 7) * 4;
        const int wr = slot >> 5, wc = (slot & 31) * 4;
        xa[l] = *(const float4*)&X[(size_t)(m0 + xr) * C_DIM + xc];
        wb[l] = *(const float4*)&W[(size_t)wr * KVN + n0 + wc];
    }

    float acc[4][4][4] = {};

    for (int k0 = 0; k0 < C_DIM; k0 += 32) {
        __syncthreads();
        #pragma unroll
        for (int l = 0; l < 4; l++) {
            const int slot = t + l * 256;
            const int xr = slot >> 3, xc = (slot & 7) * 4;
            const int wr = slot >> 5, wc = (slot & 31) * 4;
            uint32_t h0, lo0, h1, lo1;
            split2(xa[l].x, xa[l].y, h0, lo0);
            split2(xa[l].z, xa[l].w, h1, lo1);
            uint2 hv = {h0, h1}, lv = {lo0, lo1};
            *(uint2*)&XH[xr * XPAD + xc] = hv;
            *(uint2*)&XL[xr * XPAD + xc] = lv;
            split2(wb[l].x, wb[l].y, h0, lo0);
            split2(wb[l].z, wb[l].w, h1, lo1);
            uint2 hw = {h0, h1}, lw = {lo0, lo1};
            *(uint2*)&WH[wr * WPAD + wc] = hw;
            *(uint2*)&WL[wr * WPAD + wc] = lw;
        }
        __syncthreads();

        if (k0 + 32 < C_DIM) {
            #pragma unroll
            for (int l = 0; l < 4; l++) {
                const int slot = t + l * 256;
                const int xr = slot >> 3, xc = (slot & 7) * 4;
                const int wr = slot >> 5, wc = (slot & 31) * 4;
                xa[l] = *(const float4*)&X[(size_t)(m0 + xr) * C_DIM + k0 + 32 + xc];
                wb[l] = *(const float4*)&W[(size_t)(k0 + 32 + wr) * KVN + n0 + wc];
            }
        }

        #pragma unroll
        for (int ks = 0; ks < 2; ks++) {
            uint32_t ah[4][4], al[4][4];
            #pragma unroll
            for (int mi = 0; mi < 4; mi++) {
                const int addr = (a_row + mi * 16) * XPAD + ks * 16 + a_col;
                ldsm_x4(ah[mi], smem_u32(&XH[addr]));
                ldsm_x4(al[mi], smem_u32(&XL[addr]));
            }
            uint32_t bh[2][4], bl[2][4];
            #pragma unroll
            for (int nip = 0; nip < 2; nip++) {
                const int row = ks * 16 + (b_quad & 1) * 8 + b_r;
                const int col = wn * 32 + nip * 16 + (b_quad >> 1) * 8;
                ldsm_x4t(bh[nip], smem_u32(&WH[row * WPAD + col]));
                ldsm_x4t(bl[nip], smem_u32(&WL[row * WPAD + col]));
            }
            #pragma unroll
            for (int mi = 0; mi < 4; mi++)
                #pragma unroll
                for (int nn = 0; nn < 4; nn++) {
                    const uint32_t* bhp = &bh[nn >> 1][(nn & 1) * 2];
                    const uint32_t* blp = &bl[nn >> 1][(nn & 1) * 2];
                    mma16816(acc[mi][nn], ah[mi], bhp);
                    mma16816(acc[mi][nn], ah[mi], blp);
                    mma16816(acc[mi][nn], al[mi], bhp);
                }
        }
    }

    #pragma unroll
    for (int mi = 0; mi < 4; mi++)
        #pragma unroll
        for (int nn = 0; nn < 4; nn++) {
            const int row = m0 + wm * 64 + mi * 16 + g;
            const int col = n0 + wn * 32 + nn * 8 + 2 * tq;
            uint32_t hi, lo;
            split2(acc[mi][nn][0], acc[mi][nn][1], hi, lo);
            *(uint32_t*)&Oh[(size_t)row * KVN + col] = hi;
            *(uint32_t*)&Ol[(size_t)row * KVN + col] = lo;
            split2(acc[mi][nn][2], acc[mi][nn][3], hi, lo);
            *(uint32_t*)&Oh[(size_t)(row + 8) * KVN + col] = hi;
            *(uint32_t*)&Ol[(size_t)(row + 8) * KVN + col] = lo;
        }
}

// ---------------------------------------------------------------------------
// Kernel 2: fused cross attention, stage1+stage2 fused per 16-row kv slab.
// ---------------------------------------------------------------------------
constexpr int PAD = 88;
constexpr int TILE_ELE = 128 * PAD;
constexpr int ATTN_SMEM = 6 * TILE_ELE * 2;   // 135168 B

__global__ __launch_bounds__(256, 1) void attn_kernel(const float* __restrict__ x1,
                                                      const float* __restrict__ x2,
                                                      float* __restrict__ out) {
    extern __shared__ __nv_bfloat16 smb[];
    __nv_bfloat16* QH = smb;
    __nv_bfloat16* QL = smb + TILE_ELE;
    __nv_bfloat16* KH = smb + 2 * TILE_ELE;
    __nv_bfloat16* KL = smb + 3 * TILE_ELE;
    __nv_bfloat16* VH = smb + 4 * TILE_ELE;
    __nv_bfloat16* VL = smb + 5 * TILE_ELE;

    const int br = blockIdx.z;
    const int bh = blockIdx.y;
    const int bb = bh >> 3;
    const int hh = bh & 7;
    const int qt = blockIdx.x;

    const float* __restrict__ q_g = (br ? x2 : x1)
        + (size_t)bb * NSEQ * C_DIM + (size_t)qt * 128 * C_DIM + hh * HD;
    const __nv_bfloat16* __restrict__ KHg = g_kvh[1 - br];
    const __nv_bfloat16* __restrict__ KLg = g_kvl[1 - br];
    const __nv_bfloat16* __restrict__ VHg = g_kvh[br];
    const __nv_bfloat16* __restrict__ VLg = g_kvl[br];
    float* __restrict__ o_g = out + (size_t)br * NB * NSEQ * C_DIM
        + (size_t)bb * NSEQ * C_DIM + (size_t)qt * 128 * C_DIM + hh * HD;

    const int tid  = threadIdx.x;
    const int w    = tid >> 5;
    const int lane = tid & 31;
    const int g    = lane >> 2;
    const int tq   = lane & 3;

    // ---- load + scale + split q ----
    #pragma unroll
    for (int l = 0; l < 8; l++) {
        const int c   = tid + l * 256;
        const int row = c >> 4;
        const int c4  = (c & 15) * 4;
        float4 q4 = *(const float4*)&q_g[(size_t)row * C_DIM + c4];
        q4.x *= SCALE; q4.y *= SCALE; q4.z *= SCALE; q4.w *= SCALE;
        uint32_t h0, l0, h1, l1;
        split2(q4.x, q4.y, h0, l0);
        split2(q4.z, q4.w, h1, l1);
        uint2 hv = {h0, h1}, lv = {l0, l1};
        *(uint2*)&QH[row * PAD + c4] = hv;
        *(uint2*)&QL[row * PAD + c4] = lv;
    }
    __syncthreads();

    // loop-invariant Q fragments
    const int a_row_off = (lane & 7) + ((lane >> 3) & 1) * 8;
    const int a_col_off = ((lane >> 4) & 1) * 8;
    uint32_t ah[16], al[16];
    #pragma unroll
    for (int ks = 0; ks < 4; ks++) {
        const int arow = w * 16 + a_row_off;
        const int acol = ks * 16 + a_col_off;
        ldsm_x4(&ah[ks * 4], smem_u32(&QH[arow * PAD + acol]));
        ldsm_x4(&al[ks * 4], smem_u32(&QL[arow * PAD + acol]));
    }

    float oacc[8][4] = {};

    const size_t kv_row0 = (size_t)bb * NSEQ;
    const int kcol = hh * HD;
    const int vcol = C_DIM + hh * HD;
    const int b_quad = lane >> 3;
    const int b_r    = lane & 7;

    for (int mt = 0; mt < 8; mt++) {
        __syncthreads();

        const size_t rbase = kv_row0 + mt * 128;
        #pragma unroll
        for (int l = 0; l < 4; l++) {
            const int c  = tid + l * 256;
            const int m  = c >> 3;
            const int d8 = (c & 7) * 8;
            const size_t gidx = (rbase + m) * KVN;
            *(uint4*)&KH[m * PAD + d8] = *(const uint4*)&KHg[gidx + kcol + d8];
            *(uint4*)&KL[m * PAD + d8] = *(const uint4*)&KLg[gidx + kcol + d8];
            *(uint4*)&VH[m * PAD + d8] = *(const uint4*)&VHg[gidx + vcol + d8];
            *(uint4*)&VL[m * PAD + d8] = *(const uint4*)&VLg[gidx + vcol + d8];
        }
        __syncthreads();

        #pragma unroll
        for (int j = 0; j < 8; j++) {
            float s0[4] = {}, s1[4] = {};
            #pragma unroll
            for (int half = 0; half < 2; half++) {
                float* sacc = half ? s1 : s0;
                const int brow = (2 * j + half) * 8 + b_r;
                const int bcol = b_quad * 8;
                uint32_t bhf[8], blf[8];
                ldsm_x4(&bhf[0], smem_u32(&KH[brow * PAD + bcol]));
                ldsm_x4(&bhf[4], smem_u32(&KH[brow * PAD + 32 + bcol]));
                ldsm_x4(&blf[0], smem_u32(&KL[brow * PAD + bcol]));
                ldsm_x4(&blf[4], smem_u32(&KL[brow * PAD + 32 + bcol]));
                #pragma unroll
                for (int ks = 0; ks < 4; ks++) {
                    mma16816(sacc, &ah[ks * 4], &bhf[ks * 2]);
                    mma16816(sacc, &ah[ks * 4], &blf[ks * 2]);
                    mma16816(sacc, &al[ks * 4], &bhf[ks * 2]);
                }
            }

            uint32_t sah[4], sal[4];
            split2(fmaxf(s0[0], 0.0f), fmaxf(s0[1], 0.0f), sah[0], sal[0]);
            split2(fmaxf(s0[2], 0.0f), fmaxf(s0[3], 0.0f), sah[1], sal[1]);
            split2(fmaxf(s1[0], 0.0f), fmaxf(s1[1], 0.0f), sah[2], sal[2]);
            split2(fmaxf(s1[2], 0.0f), fmaxf(s1[3], 0.0f), sah[3], sal[3]);

            const int vrow = j * 16 + (b_quad & 1) * 8 + b_r;
            #pragma unroll
            for (int np = 0; np < 4; np++) {
                const int col = np * 16 + (b_quad >> 1) * 8;
                uint32_t bvh[4], bvl[4];
                ldsm_x4t(bvh, smem_u32(&VH[vrow * PAD + col]));
                ldsm_x4t(bvl, smem_u32(&VL[vrow * PAD + col]));
                mma16816(oacc[2 * np],     sah, &bvh[0]);
                mma16816(oacc[2 * np],     sah, &bvl[0]);
                mma16816(oacc[2 * np],     sal, &bvh[0]);
                mma16816(oacc[2 * np + 1], sah, &bvh[2]);
                mma16816(oacc[2 * np + 1], sah, &bvl[2]);
                mma16816(oacc[2 * np + 1], sal, &bvh[2]);
            }
        }
    }

    #pragma unroll
    for (int nt2 = 0; nt2 < 8; nt2++) {
        float2 v0 = {oacc[nt2][0], oacc[nt2][1]};
        float2 v1 = {oacc[nt2][2], oacc[nt2][3]};
        *(float2*)&o_g[(size_t)(w * 16 + g) * C_DIM + nt2 * 8 + 2 * tq] = v0;
        *(float2*)&o_g[(size_t)(w * 16 + g + 8) * C_DIM + nt2 * 8 + 2 * tq] = v1;
    }
}

// ---------------------------------------------------------------------------
extern "C" void kernel_launch(void* const* d_in, const int* in_sizes, int n_in,
                              void* d_out, int out_size) {
    const float* x1 = (const float*)d_in[0];
    const float* x2 = (const float*)d_in[1];
    const float* w1 = (const float*)d_in[2];
    const float* w2 = (const float*)d_in[3];
    float* out = (float*)d_out;

    (void)cudaFuncSetAttribute(attn_kernel,
                               cudaFuncAttributeMaxDynamicSharedMemorySize, ATTN_SMEM);

    dim3 g1(KVN / 128, M_TOT / 128, 2);     // (8, 64, 2)
    kv_gemm<<<g1, 256>>>(x1, x2, w1, w2);

    dim3 g2(NSEQ / 128, NB * NHEADS, 2);    // (8, 64, 2)
    attn_kernel<<<g2, 256, ATTN_SMEM>>>(x1, x2, out);
}

// round 7
// speedup vs baseline: 4.3300x; 1.0237x over previous
#include <cuda_runtime.h>
#include <cuda_bf16.h>
#include <cstdint>

constexpr int C_DIM  = 512;
constexpr int NHEADS = 8;
constexpr int HD     = 64;
constexpr int NB     = 8;
constexpr int NSEQ   = 1024;
constexpr int M_TOT  = NB * NSEQ;     // 8192
constexpr int KVN    = 2 * C_DIM;     // 1024
constexpr float SCALE = 0.125f;

// kv results as bf16 hi/lo planes
__device__ __nv_bfloat16 g_kvh[2][(size_t)M_TOT * KVN];
__device__ __nv_bfloat16 g_kvl[2][(size_t)M_TOT * KVN];
// pre-split GEMM inputs
__device__ __nv_bfloat16 g_xh[2][(size_t)M_TOT * C_DIM];
__device__ __nv_bfloat16 g_xl[2][(size_t)M_TOT * C_DIM];
__device__ __nv_bfloat16 g_wh[2][(size_t)C_DIM * KVN];
__device__ __nv_bfloat16 g_wl[2][(size_t)C_DIM * KVN];

// ---------------------------------------------------------------------------
__device__ __forceinline__ uint32_t smem_u32(const void* p) {
    return (uint32_t)__cvta_generic_to_shared(p);
}
__device__ __forceinline__ void ldsm_x4(uint32_t* r, uint32_t a) {
    asm volatile("ldmatrix.sync.aligned.m8n8.x4.shared.b16 {%0,%1,%2,%3}, [%4];"
                 : "=r"(r[0]), "=r"(r[1]), "=r"(r[2]), "=r"(r[3]) : "r"(a));
}
__device__ __forceinline__ void ldsm_x4t(uint32_t* r, uint32_t a) {
    asm volatile("ldmatrix.sync.aligned.m8n8.x4.trans.shared.b16 {%0,%1,%2,%3}, [%4];"
                 : "=r"(r[0]), "=r"(r[1]), "=r"(r[2]), "=r"(r[3]) : "r"(a));
}
__device__ __forceinline__ void mma16816(float* c, const uint32_t* a, const uint32_t* b) {
    asm volatile("mma.sync.aligned.m16n8k16.row.col.f32.bf16.bf16.f32 "
                 "{%0,%1,%2,%3}, {%4,%5,%6,%7}, {%8,%9}, {%0,%1,%2,%3};"
                 : "+f"(c[0]), "+f"(c[1]), "+f"(c[2]), "+f"(c[3])
                 : "r"(a[0]), "r"(a[1]), "r"(a[2]), "r"(a[3]), "r"(b[0]), "r"(b[1]));
}
__device__ __forceinline__ void split2(float x0, float x1, uint32_t& hi, uint32_t& lo) {
    __nv_bfloat16 h0 = __float2bfloat16_rn(x0);
    __nv_bfloat16 h1 = __float2bfloat16_rn(x1);
    __nv_bfloat162 hp; hp.x = h0; hp.y = h1;
    __nv_bfloat162 lp;
    lp.x = __float2bfloat16_rn(x0 - __bfloat162float(h0));
    lp.y = __float2bfloat16_rn(x1 - __bfloat162float(h1));
    hi = *reinterpret_cast<uint32_t*>(&hp);
    lo = *reinterpret_cast<uint32_t*>(&lp);
}
__device__ __forceinline__ void cp16(uint32_t s, const void* g) {
    asm volatile("cp.async.cg.shared.global [%0], [%1], 16;" :: "r"(s), "l"(g));
}
__device__ __forceinline__ void cp_commit() {
    asm volatile("cp.async.commit_group;");
}
__device__ __forceinline__ void cp_wait0() {
    asm volatile("cp.async.wait_group 0;");
}

// ---------------------------------------------------------------------------
// Kernel 0: split fp32 -> bf16 hi/lo planes (elementwise, vec4)
// ---------------------------------------------------------------------------
__global__ __launch_bounds__(256) void split_kernel(const float* __restrict__ src,
                                                    __nv_bfloat16* __restrict__ dh,
                                                    __nv_bfloat16* __restrict__ dl,
                                                    int n4) {
    const int i = blockIdx.x * blockDim.x + threadIdx.x;
    if (i >= n4) return;
    const float4 v = *(const float4*)&src[i * 4];
    uint32_t h0, l0, h1, l1;
    split2(v.x, v.y, h0, l0);
    split2(v.z, v.w, h1, l1);
    uint2 hv = {h0, h1}, lv = {l0, l1};
    *(uint2*)&dh[i * 4] = hv;
    *(uint2*)&dl[i * 4] = lv;
}

// ---------------------------------------------------------------------------
// Kernel 1: kv = x @ W on tensor cores; inputs pre-split, cp.async 2-stage.
// 128x128 CTA tile, K-step 32. Warp tile 64x32. Dynamic smem (75776 B).
// Layout (bf16 elements, per stage p in {0,1}):
//   XH: p*5120,  XL: 10240 + p*5120          (128 x XPAD each)
//   WH: 20480 + p*4352,  WL: 29184 + p*4352  (32 x WPAD each)
// ---------------------------------------------------------------------------
constexpr int XPAD = 40;
constexpr int WPAD = 136;
constexpr int XT = 128 * XPAD;         // 5120
constexpr int WT = 32 * WPAD;          // 4352
constexpr int KV_SMEM = (4 * XT + 4 * WT) * 2;   // 75776 B

__global__ __launch_bounds__(256, 1) void kv_gemm(int dummy) {
    extern __shared__ __nv_bfloat16 ksm[];
    const int br = blockIdx.z;
    const __nv_bfloat16* __restrict__ XH_g = g_xh[br];
    const __nv_bfloat16* __restrict__ XL_g = g_xl[br];
    const __nv_bfloat16* __restrict__ WH_g = g_wh[br];
    const __nv_bfloat16* __restrict__ WL_g = g_wl[br];
    __nv_bfloat16* __restrict__ Oh = g_kvh[br];
    __nv_bfloat16* __restrict__ Ol = g_kvl[br];

    const int t    = threadIdx.x;
    const int w    = t >> 5;
    const int lane = t & 31;
    const int g    = lane >> 2;
    const int tq   = lane & 3;
    const int wm   = w >> 2;
    const int wn   = w & 3;
    const int m0   = blockIdx.y * 128;
    const int n0   = blockIdx.x * 128;

    const int a_row = wm * 64 + (lane & 7) + ((lane >> 3) & 1) * 8;
    const int a_col = ((lane >> 4) & 1) * 8;
    const int b_quad = lane >> 3;
    const int b_r    = lane & 7;

    const int xr0 = (t + 0)   >> 2, xc0 = ((t + 0)   & 3) * 8;
    const int xr1 = (t + 256) >> 2, xc1 = ((t + 256) & 3) * 8;
    const int wr0 = (t + 0)   >> 4, wc0 = ((t + 0)   & 15) * 8;
    const int wr1 = (t + 256) >> 4, wc1 = ((t + 256) & 15) * 8;

    auto issue = [&](int k0, int p) {
        __nv_bfloat16* XH = ksm + p * XT;
        __nv_bfloat16* XL = ksm + 2 * XT + p * XT;
        __nv_bfloat16* WH = ksm + 4 * XT + p * WT;
        __nv_bfloat16* WL = ksm + 4 * XT + 2 * WT + p * WT;
        cp16(smem_u32(&XH[xr0 * XPAD + xc0]), &XH_g[(size_t)(m0 + xr0) * C_DIM + k0 + xc0]);
        cp16(smem_u32(&XH[xr1 * XPAD + xc1]), &XH_g[(size_t)(m0 + xr1) * C_DIM + k0 + xc1]);
        cp16(smem_u32(&XL[xr0 * XPAD + xc0]), &XL_g[(size_t)(m0 + xr0) * C_DIM + k0 + xc0]);
        cp16(smem_u32(&XL[xr1 * XPAD + xc1]), &XL_g[(size_t)(m0 + xr1) * C_DIM + k0 + xc1]);
        cp16(smem_u32(&WH[wr0 * WPAD + wc0]), &WH_g[(size_t)(k0 + wr0) * KVN + n0 + wc0]);
        cp16(smem_u32(&WH[wr1 * WPAD + wc1]), &WH_g[(size_t)(k0 + wr1) * KVN + n0 + wc1]);
        cp16(smem_u32(&WL[wr0 * WPAD + wc0]), &WL_g[(size_t)(k0 + wr0) * KVN + n0 + wc0]);
        cp16(smem_u32(&WL[wr1 * WPAD + wc1]), &WL_g[(size_t)(k0 + wr1) * KVN + n0 + wc1]);
        cp_commit();
    };

    float acc[4][4][4] = {};

    issue(0, 0);
    for (int ki = 0; ki < 16; ki++) {
        cp_wait0();
        __syncthreads();
        if (ki + 1 < 16) issue((ki + 1) * 32, (ki + 1) & 1);
        const int p = ki & 1;
        const __nv_bfloat16* XH = ksm + p * XT;
        const __nv_bfloat16* XL = ksm + 2 * XT + p * XT;
        const __nv_bfloat16* WH = ksm + 4 * XT + p * WT;
        const __nv_bfloat16* WL = ksm + 4 * XT + 2 * WT + p * WT;

        #pragma unroll
        for (int ks = 0; ks < 2; ks++) {
            uint32_t ah[4][4], al[4][4];
            #pragma unroll
            for (int mi = 0; mi < 4; mi++) {
                const int addr = (a_row + mi * 16) * XPAD + ks * 16 + a_col;
                ldsm_x4(ah[mi], smem_u32(&XH[addr]));
                ldsm_x4(al[mi], smem_u32(&XL[addr]));
            }
            uint32_t bh[2][4], bl[2][4];
            #pragma unroll
            for (int nip = 0; nip < 2; nip++) {
                const int row = ks * 16 + (b_quad & 1) * 8 + b_r;
                const int col = wn * 32 + nip * 16 + (b_quad >> 1) * 8;
                ldsm_x4t(bh[nip], smem_u32(&WH[row * WPAD + col]));
                ldsm_x4t(bl[nip], smem_u32(&WL[row * WPAD + col]));
            }
            #pragma unroll
            for (int mi = 0; mi < 4; mi++)
                #pragma unroll
                for (int nn = 0; nn < 4; nn++) {
                    const uint32_t* bhp = &bh[nn >> 1][(nn & 1) * 2];
                    const uint32_t* blp = &bl[nn >> 1][(nn & 1) * 2];
                    mma16816(acc[mi][nn], ah[mi], bhp);
                    mma16816(acc[mi][nn], ah[mi], blp);
                    mma16816(acc[mi][nn], al[mi], bhp);
                }
        }
        __syncthreads();
    }

    #pragma unroll
    for (int mi = 0; mi < 4; mi++)
        #pragma unroll
        for (int nn = 0; nn < 4; nn++) {
            const int row = m0 + wm * 64 + mi * 16 + g;
            const int col = n0 + wn * 32 + nn * 8 + 2 * tq;
            uint32_t hi, lo;
            split2(acc[mi][nn][0], acc[mi][nn][1], hi, lo);
            *(uint32_t*)&Oh[(size_t)row * KVN + col] = hi;
            *(uint32_t*)&Ol[(size_t)row * KVN + col] = lo;
            split2(acc[mi][nn][2], acc[mi][nn][3], hi, lo);
            *(uint32_t*)&Oh[(size_t)(row + 8) * KVN + col] = hi;
            *(uint32_t*)&Ol[(size_t)(row + 8) * KVN + col] = lo;
        }
}

// ---------------------------------------------------------------------------
// Kernel 2: fused cross attention; cp.async double-buffered K/V,
// interleaved S half-chains.
// smem: QH QL + 2 x (KH KL VH VL) = 10 planes of 128x88 bf16 = 225280 B.
// ---------------------------------------------------------------------------
constexpr int PAD = 88;
constexpr int TILE_ELE = 128 * PAD;
constexpr int ATTN_SMEM = 10 * TILE_ELE * 2;   // 225280 B

__global__ __launch_bounds__(256, 1) void attn_kernel(const float* __restrict__ x1,
                                                      const float* __restrict__ x2,
                                                      float* __restrict__ out) {
    extern __shared__ __nv_bfloat16 smb[];
    __nv_bfloat16* QH = smb;
    __nv_bfloat16* QL = smb + TILE_ELE;

    const int br = blockIdx.z;
    const int bh = blockIdx.y;
    const int bb = bh >> 3;
    const int hh = bh & 7;
    const int qt = blockIdx.x;

    const float* __restrict__ q_g = (br ? x2 : x1)
        + (size_t)bb * NSEQ * C_DIM + (size_t)qt * 128 * C_DIM + hh * HD;
    const __nv_bfloat16* __restrict__ KHg = g_kvh[1 - br];
    const __nv_bfloat16* __restrict__ KLg = g_kvl[1 - br];
    const __nv_bfloat16* __restrict__ VHg = g_kvh[br];
    const __nv_bfloat16* __restrict__ VLg = g_kvl[br];
    float* __restrict__ o_g = out + (size_t)br * NB * NSEQ * C_DIM
        + (size_t)bb * NSEQ * C_DIM + (size_t)qt * 128 * C_DIM + hh * HD;

    const int tid  = threadIdx.x;
    const int w    = tid >> 5;
    const int lane = tid & 31;
    const int g    = lane >> 2;
    const int tq   = lane & 3;

    const size_t kv_row0 = (size_t)bb * NSEQ;
    const int kcol = hh * HD;
    const int vcol = C_DIM + hh * HD;

    int cm[4], cd[4];
    #pragma unroll
    for (int l = 0; l < 4; l++) {
        const int c = tid + l * 256;
        cm[l] = c >> 3;
        cd[l] = (c & 7) * 8;
    }

    auto issue = [&](int mt, int p) {
        __nv_bfloat16* KH = smb + (2 + p * 4 + 0) * TILE_ELE;
        __nv_bfloat16* KL = smb + (2 + p * 4 + 1) * TILE_ELE;
        __nv_bfloat16* VH = smb + (2 + p * 4 + 2) * TILE_ELE;
        __nv_bfloat16* VL = smb + (2 + p * 4 + 3) * TILE_ELE;
        const size_t rbase = kv_row0 + (size_t)mt * 128;
        #pragma unroll
        for (int l = 0; l < 4; l++) {
            const size_t gidx = (rbase + cm[l]) * KVN;
            const int so = cm[l] * PAD + cd[l];
            cp16(smem_u32(&KH[so]), &KHg[gidx + kcol + cd[l]]);
            cp16(smem_u32(&KL[so]), &KLg[gidx + kcol + cd[l]]);
            cp16(smem_u32(&VH[so]), &VHg[gidx + vcol + cd[l]]);
            cp16(smem_u32(&VL[so]), &VLg[gidx + vcol + cd[l]]);
        }
        cp_commit();
    };

    // ---- prologue: issue tile 0, load + scale + split Q ----
    issue(0, 0);
    #pragma unroll
    for (int l = 0; l < 8; l++) {
        const int c   = tid + l * 256;
        const int row = c >> 4;
        const int c4  = (c & 15) * 4;
        float4 q4 = *(const float4*)&q_g[(size_t)row * C_DIM + c4];
        q4.x *= SCALE; q4.y *= SCALE; q4.z *= SCALE; q4.w *= SCALE;
        uint32_t h0, l0, h1, l1;
        split2(q4.x, q4.y, h0, l0);
        split2(q4.z, q4.w, h1, l1);
        uint2 hv = {h0, h1}, lv = {l0, l1};
        *(uint2*)&QH[row * PAD + c4] = hv;
        *(uint2*)&QL[row * PAD + c4] = lv;
    }
    __syncthreads();

    const int a_row_off = (lane & 7) + ((lane >> 3) & 1) * 8;
    const int a_col_off = ((lane >> 4) & 1) * 8;
    uint32_t ah[16], al[16];
    #pragma unroll
    for (int ks = 0; ks < 4; ks++) {
        const int arow = w * 16 + a_row_off;
        const int acol = ks * 16 + a_col_off;
        ldsm_x4(&ah[ks * 4], smem_u32(&QH[arow * PAD + acol]));
        ldsm_x4(&al[ks * 4], smem_u32(&QL[arow * PAD + acol]));
    }

    float oacc[8][4] = {};
    const int b_quad = lane >> 3;
    const int b_r    = lane & 7;

    for (int mt = 0; mt < 8; mt++) {
        cp_wait0();
        __syncthreads();
        if (mt + 1 < 8) issue(mt + 1, (mt + 1) & 1);

        const int p = mt & 1;
        const __nv_bfloat16* KH = smb + (2 + p * 4 + 0) * TILE_ELE;
        const __nv_bfloat16* KL = smb + (2 + p * 4 + 1) * TILE_ELE;
        const __nv_bfloat16* VH = smb + (2 + p * 4 + 2) * TILE_ELE;
        const __nv_bfloat16* VL = smb + (2 + p * 4 + 3) * TILE_ELE;

        #pragma unroll
        for (int j = 0; j < 8; j++) {
            const int bcol  = b_quad * 8;
            const int brow0 = (2 * j + 0) * 8 + b_r;
            const int brow1 = (2 * j + 1) * 8 + b_r;
            uint32_t bh0[8], bl0[8], bh1[8], bl1[8];
            ldsm_x4(&bh0[0], smem_u32(&KH[brow0 * PAD + bcol]));
            ldsm_x4(&bh0[4], smem_u32(&KH[brow0 * PAD + 32 + bcol]));
            ldsm_x4(&bl0[0], smem_u32(&KL[brow0 * PAD + bcol]));
            ldsm_x4(&bl0[4], smem_u32(&KL[brow0 * PAD + 32 + bcol]));
            ldsm_x4(&bh1[0], smem_u32(&KH[brow1 * PAD + bcol]));
            ldsm_x4(&bh1[4], smem_u32(&KH[brow1 * PAD + 32 + bcol]));
            ldsm_x4(&bl1[0], smem_u32(&KL[brow1 * PAD + bcol]));
            ldsm_x4(&bl1[4], smem_u32(&KL[brow1 * PAD + 32 + bcol]));

            float s0[4] = {}, s1[4] = {};
            #pragma unroll
            for (int ks = 0; ks < 4; ks++) {
                mma16816(s0, &ah[ks * 4], &bh0[ks * 2]);
                mma16816(s1, &ah[ks * 4], &bh1[ks * 2]);
                mma16816(s0, &ah[ks * 4], &bl0[ks * 2]);
                mma16816(s1, &ah[ks * 4], &bl1[ks * 2]);
                mma16816(s0, &al[ks * 4], &bh0[ks * 2]);
                mma16816(s1, &al[ks * 4], &bh1[ks * 2]);
            }

            uint32_t sah[4], sal[4];
            split2(fmaxf(s0[0], 0.0f), fmaxf(s0[1], 0.0f), sah[0], sal[0]);
            split2(fmaxf(s0[2], 0.0f), fmaxf(s0[3], 0.0f), sah[1], sal[1]);
            split2(fmaxf(s1[0], 0.0f), fmaxf(s1[1], 0.0f), sah[2], sal[2]);
            split2(fmaxf(s1[2], 0.0f), fmaxf(s1[3], 0.0f), sah[3], sal[3]);

            const int vrow = j * 16 + (b_quad & 1) * 8 + b_r;
            #pragma unroll
            for (int np = 0; np < 4; np++) {
                const int col = np * 16 + (b_quad >> 1) * 8;
                uint32_t bvh[4], bvl[4];
                ldsm_x4t(bvh, smem_u32(&VH[vrow * PAD + col]));
                ldsm_x4t(bvl, smem_u32(&VL[vrow * PAD + col]));
                mma16816(oacc[2 * np],     sah, &bvh[0]);
                mma16816(oacc[2 * np + 1], sah, &bvh[2]);
                mma16816(oacc[2 * np],     sah, &bvl[0]);
                mma16816(oacc[2 * np + 1], sah, &bvl[2]);
                mma16816(oacc[2 * np],     sal, &bvh[0]);
                mma16816(oacc[2 * np + 1], sal, &bvh[2]);
            }
        }
        __syncthreads();
    }

    #pragma unroll
    for (int nt2 = 0; nt2 < 8; nt2++) {
        float2 v0 = {oacc[nt2][0], oacc[nt2][1]};
        float2 v1 = {oacc[nt2][2], oacc[nt2][3]};
        *(float2*)&o_g[(size_t)(w * 16 + g) * C_DIM + nt2 * 8 + 2 * tq] = v0;
        *(float2*)&o_g[(size_t)(w * 16 + g + 8) * C_DIM + nt2 * 8 + 2 * tq] = v1;
    }
}

// ---------------------------------------------------------------------------
extern "C" void kernel_launch(void* const* d_in, const int* in_sizes, int n_in,
                              void* d_out, int out_size) {
    const float* x1 = (const float*)d_in[0];
    const float* x2 = (const float*)d_in[1];
    const float* w1 = (const float*)d_in[2];
    const float* w2 = (const float*)d_in[3];
    float* out = (float*)d_out;

    (void)cudaFuncSetAttribute(attn_kernel,
                               cudaFuncAttributeMaxDynamicSharedMemorySize, ATTN_SMEM);
    (void)cudaFuncSetAttribute(kv_gemm,
                               cudaFuncAttributeMaxDynamicSharedMemorySize, KV_SMEM);

    __nv_bfloat16 *xh0, *xl0, *wh0, *wl0;
    (void)cudaGetSymbolAddress((void**)&xh0, g_xh);
    (void)cudaGetSymbolAddress((void**)&xl0, g_xl);
    (void)cudaGetSymbolAddress((void**)&wh0, g_wh);
    (void)cudaGetSymbolAddress((void**)&wl0, g_wl);
    __nv_bfloat16* xh1 = xh0 + (size_t)M_TOT * C_DIM;
    __nv_bfloat16* xl1 = xl0 + (size_t)M_TOT * C_DIM;
    __nv_bfloat16* wh1 = wh0 + (size_t)C_DIM * KVN;
    __nv_bfloat16* wl1 = wl0 + (size_t)C_DIM * KVN;

    const int xn4 = M_TOT * C_DIM / 4;
    const int wn4 = C_DIM * KVN / 4;
    split_kernel<<<(xn4 + 255) / 256, 256>>>(x1, xh0, xl0, xn4);
    split_kernel<<<(xn4 + 255) / 256, 256>>>(x2, xh1, xl1, xn4);
    split_kernel<<<(wn4 + 255) / 256, 256>>>(w1, wh0, wl0, wn4);
    split_kernel<<<(wn4 + 255) / 256, 256>>>(w2, wh1, wl1, wn4);

    dim3 g1(KVN / 128, M_TOT / 128, 2);
    kv_gemm<<<g1, 256, KV_SMEM>>>(0);

    dim3 g2(NSEQ / 128, NB * NHEADS, 2);
    attn_kernel<<<g2, 256, ATTN_SMEM>>>(x1, x2, out);
}

// round 8
// speedup vs baseline: 4.3660x; 1.0083x over previous
#include <cuda_runtime.h>
#include <cuda_bf16.h>
#include <cstdint>

constexpr int C_DIM  = 512;
constexpr int NHEADS = 8;
constexpr int HD     = 64;
constexpr int NB     = 8;
constexpr int NSEQ   = 1024;
constexpr int M_TOT  = NB * NSEQ;     // 8192
constexpr int KVN    = 2 * C_DIM;     // 1024
constexpr float SCALE = 0.125f;

// kv results as bf16 hi/lo planes
__device__ __nv_bfloat16 g_kvh[2][(size_t)M_TOT * KVN];
__device__ __nv_bfloat16 g_kvl[2][(size_t)M_TOT * KVN];
// pre-split GEMM inputs
__device__ __nv_bfloat16 g_xh[2][(size_t)M_TOT * C_DIM];
__device__ __nv_bfloat16 g_xl[2][(size_t)M_TOT * C_DIM];
__device__ __nv_bfloat16 g_wh[2][(size_t)C_DIM * KVN];
__device__ __nv_bfloat16 g_wl[2][(size_t)C_DIM * KVN];

// ---------------------------------------------------------------------------
__device__ __forceinline__ uint32_t smem_u32(const void* p) {
    return (uint32_t)__cvta_generic_to_shared(p);
}
__device__ __forceinline__ void ldsm_x4(uint32_t* r, uint32_t a) {
    asm volatile("ldmatrix.sync.aligned.m8n8.x4.shared.b16 {%0,%1,%2,%3}, [%4];"
                 : "=r"(r[0]), "=r"(r[1]), "=r"(r[2]), "=r"(r[3]) : "r"(a));
}
__device__ __forceinline__ void ldsm_x4t(uint32_t* r, uint32_t a) {
    asm volatile("ldmatrix.sync.aligned.m8n8.x4.trans.shared.b16 {%0,%1,%2,%3}, [%4];"
                 : "=r"(r[0]), "=r"(r[1]), "=r"(r[2]), "=r"(r[3]) : "r"(a));
}
__device__ __forceinline__ void mma16816(float* c, const uint32_t* a, const uint32_t* b) {
    asm volatile("mma.sync.aligned.m16n8k16.row.col.f32.bf16.bf16.f32 "
                 "{%0,%1,%2,%3}, {%4,%5,%6,%7}, {%8,%9}, {%0,%1,%2,%3};"
                 : "+f"(c[0]), "+f"(c[1]), "+f"(c[2]), "+f"(c[3])
                 : "r"(a[0]), "r"(a[1]), "r"(a[2]), "r"(a[3]), "r"(b[0]), "r"(b[1]));
}
__device__ __forceinline__ void split2(float x0, float x1, uint32_t& hi, uint32_t& lo) {
    __nv_bfloat16 h0 = __float2bfloat16_rn(x0);
    __nv_bfloat16 h1 = __float2bfloat16_rn(x1);
    __nv_bfloat162 hp; hp.x = h0; hp.y = h1;
    __nv_bfloat162 lp;
    lp.x = __float2bfloat16_rn(x0 - __bfloat162float(h0));
    lp.y = __float2bfloat16_rn(x1 - __bfloat162float(h1));
    hi = *reinterpret_cast<uint32_t*>(&hp);
    lo = *reinterpret_cast<uint32_t*>(&lp);
}
__device__ __forceinline__ void cp16(uint32_t s, const void* g) {
    asm volatile("cp.async.cg.shared.global [%0], [%1], 16;" :: "r"(s), "l"(g));
}
__device__ __forceinline__ void cp_commit() {
    asm volatile("cp.async.commit_group;");
}
__device__ __forceinline__ void cp_wait0() {
    asm volatile("cp.async.wait_group 0;");
}

// ---------------------------------------------------------------------------
// Kernel 0: split ALL fp32 inputs -> bf16 hi/lo planes in one launch.
// Chunk layout: [x1 | x2 | w1 | w2], each chunk = 4 floats.
// ---------------------------------------------------------------------------
constexpr int XN4 = M_TOT * C_DIM / 4;    // 1,048,576 chunks per x tensor
constexpr int WN4 = C_DIM * KVN / 4;      // 131,072 chunks per w tensor
constexpr int TOT4 = 2 * XN4 + 2 * WN4;   // 2,359,296

__global__ __launch_bounds__(256) void split_all(const float* __restrict__ x1,
                                                 const float* __restrict__ x2,
                                                 const float* __restrict__ w1,
                                                 const float* __restrict__ w2,
                                                 __nv_bfloat16* __restrict__ xh,
                                                 __nv_bfloat16* __restrict__ xl,
                                                 __nv_bfloat16* __restrict__ wh,
                                                 __nv_bfloat16* __restrict__ wl) {
    const int i = blockIdx.x * blockDim.x + threadIdx.x;
    if (i >= TOT4) return;
    const float* s;
    __nv_bfloat16 *dh, *dl;
    size_t off;
    if (i < XN4)            { s = x1; dh = xh; dl = xl; off = i; }
    else if (i < 2 * XN4)   { s = x2; dh = xh + (size_t)M_TOT * C_DIM; dl = xl + (size_t)M_TOT * C_DIM; off = i - XN4; }
    else if (i < 2 * XN4 + WN4) { s = w1; dh = wh; dl = wl; off = i - 2 * XN4; }
    else                    { s = w2; dh = wh + (size_t)C_DIM * KVN; dl = wl + (size_t)C_DIM * KVN; off = i - 2 * XN4 - WN4; }
    const float4 v = *(const float4*)&s[off * 4];
    uint32_t h0, l0, h1, l1;
    split2(v.x, v.y, h0, l0);
    split2(v.z, v.w, h1, l1);
    uint2 hv = {h0, h1}, lv = {l0, l1};
    *(uint2*)&dh[off * 4] = hv;
    *(uint2*)&dl[off * 4] = lv;
}

// ---------------------------------------------------------------------------
// Kernel 1: kv = x @ W on tensor cores; inputs pre-split, cp.async 2-stage.
// ---------------------------------------------------------------------------
constexpr int XPAD = 40;
constexpr int WPAD = 136;
constexpr int XT = 128 * XPAD;         // 5120
constexpr int WT = 32 * WPAD;          // 4352
constexpr int KV_SMEM = (4 * XT + 4 * WT) * 2;   // 75776 B

__global__ __launch_bounds__(256, 1) void kv_gemm(int dummy) {
    extern __shared__ __nv_bfloat16 ksm[];
    const int br = blockIdx.z;
    const __nv_bfloat16* __restrict__ XH_g = g_xh[br];
    const __nv_bfloat16* __restrict__ XL_g = g_xl[br];
    const __nv_bfloat16* __restrict__ WH_g = g_wh[br];
    const __nv_bfloat16* __restrict__ WL_g = g_wl[br];
    __nv_bfloat16* __restrict__ Oh = g_kvh[br];
    __nv_bfloat16* __restrict__ Ol = g_kvl[br];

    const int t    = threadIdx.x;
    const int w    = t >> 5;
    const int lane = t & 31;
    const int g    = lane >> 2;
    const int tq   = lane & 3;
    const int wm   = w >> 2;
    const int wn   = w & 3;
    const int m0   = blockIdx.y * 128;
    const int n0   = blockIdx.x * 128;

    const int a_row = wm * 64 + (lane & 7) + ((lane >> 3) & 1) * 8;
    const int a_col = ((lane >> 4) & 1) * 8;
    const int b_quad = lane >> 3;
    const int b_r    = lane & 7;

    const int xr0 = (t + 0)   >> 2, xc0 = ((t + 0)   & 3) * 8;
    const int xr1 = (t + 256) >> 2, xc1 = ((t + 256) & 3) * 8;
    const int wr0 = (t + 0)   >> 4, wc0 = ((t + 0)   & 15) * 8;
    const int wr1 = (t + 256) >> 4, wc1 = ((t + 256) & 15) * 8;

    auto issue = [&](int k0, int p) {
        __nv_bfloat16* XH = ksm + p * XT;
        __nv_bfloat16* XL = ksm + 2 * XT + p * XT;
        __nv_bfloat16* WH = ksm + 4 * XT + p * WT;
        __nv_bfloat16* WL = ksm + 4 * XT + 2 * WT + p * WT;
        cp16(smem_u32(&XH[xr0 * XPAD + xc0]), &XH_g[(size_t)(m0 + xr0) * C_DIM + k0 + xc0]);
        cp16(smem_u32(&XH[xr1 * XPAD + xc1]), &XH_g[(size_t)(m0 + xr1) * C_DIM + k0 + xc1]);
        cp16(smem_u32(&XL[xr0 * XPAD + xc0]), &XL_g[(size_t)(m0 + xr0) * C_DIM + k0 + xc0]);
        cp16(smem_u32(&XL[xr1 * XPAD + xc1]), &XL_g[(size_t)(m0 + xr1) * C_DIM + k0 + xc1]);
        cp16(smem_u32(&WH[wr0 * WPAD + wc0]), &WH_g[(size_t)(k0 + wr0) * KVN + n0 + wc0]);
        cp16(smem_u32(&WH[wr1 * WPAD + wc1]), &WH_g[(size_t)(k0 + wr1) * KVN + n0 + wc1]);
        cp16(smem_u32(&WL[wr0 * WPAD + wc0]), &WL_g[(size_t)(k0 + wr0) * KVN + n0 + wc0]);
        cp16(smem_u32(&WL[wr1 * WPAD + wc1]), &WL_g[(size_t)(k0 + wr1) * KVN + n0 + wc1]);
        cp_commit();
    };

    float acc[4][4][4] = {};

    issue(0, 0);
    for (int ki = 0; ki < 16; ki++) {
        cp_wait0();
        __syncthreads();
        if (ki + 1 < 16) issue((ki + 1) * 32, (ki + 1) & 1);
        const int p = ki & 1;
        const __nv_bfloat16* XH = ksm + p * XT;
        const __nv_bfloat16* XL = ksm + 2 * XT + p * XT;
        const __nv_bfloat16* WH = ksm + 4 * XT + p * WT;
        const __nv_bfloat16* WL = ksm + 4 * XT + 2 * WT + p * WT;

        #pragma unroll
        for (int ks = 0; ks < 2; ks++) {
            uint32_t ah[4][4], al[4][4];
            #pragma unroll
            for (int mi = 0; mi < 4; mi++) {
                const int addr = (a_row + mi * 16) * XPAD + ks * 16 + a_col;
                ldsm_x4(ah[mi], smem_u32(&XH[addr]));
                ldsm_x4(al[mi], smem_u32(&XL[addr]));
            }
            uint32_t bh[2][4], bl[2][4];
            #pragma unroll
            for (int nip = 0; nip < 2; nip++) {
                const int row = ks * 16 + (b_quad & 1) * 8 + b_r;
                const int col = wn * 32 + nip * 16 + (b_quad >> 1) * 8;
                ldsm_x4t(bh[nip], smem_u32(&WH[row * WPAD + col]));
                ldsm_x4t(bl[nip], smem_u32(&WL[row * WPAD + col]));
            }
            #pragma unroll
            for (int mi = 0; mi < 4; mi++)
                #pragma unroll
                for (int nn = 0; nn < 4; nn++) {
                    const uint32_t* bhp = &bh[nn >> 1][(nn & 1) * 2];
                    const uint32_t* blp = &bl[nn >> 1][(nn & 1) * 2];
                    mma16816(acc[mi][nn], ah[mi], bhp);
                    mma16816(acc[mi][nn], ah[mi], blp);
                    mma16816(acc[mi][nn], al[mi], bhp);
                }
        }
        __syncthreads();
    }

    #pragma unroll
    for (int mi = 0; mi < 4; mi++)
        #pragma unroll
        for (int nn = 0; nn < 4; nn++) {
            const int row = m0 + wm * 64 + mi * 16 + g;
            const int col = n0 + wn * 32 + nn * 8 + 2 * tq;
            uint32_t hi, lo;
            split2(acc[mi][nn][0], acc[mi][nn][1], hi, lo);
            *(uint32_t*)&Oh[(size_t)row * KVN + col] = hi;
            *(uint32_t*)&Ol[(size_t)row * KVN + col] = lo;
            split2(acc[mi][nn][2], acc[mi][nn][3], hi, lo);
            *(uint32_t*)&Oh[(size_t)(row + 8) * KVN + col] = hi;
            *(uint32_t*)&Ol[(size_t)(row + 8) * KVN + col] = lo;
        }
}

// ---------------------------------------------------------------------------
// Kernel 2: fused cross attention; 6 independent stage-1 mma chains.
// ---------------------------------------------------------------------------
constexpr int PAD = 88;
constexpr int TILE_ELE = 128 * PAD;
constexpr int ATTN_SMEM = 10 * TILE_ELE * 2;   // 225280 B

__global__ __launch_bounds__(256, 1) void attn_kernel(const float* __restrict__ x1,
                                                      const float* __restrict__ x2,
                                                      float* __restrict__ out) {
    extern __shared__ __nv_bfloat16 smb[];
    __nv_bfloat16* QH = smb;
    __nv_bfloat16* QL = smb + TILE_ELE;

    const int br = blockIdx.z;
    const int bh = blockIdx.y;
    const int bb = bh >> 3;
    const int hh = bh & 7;
    const int qt = blockIdx.x;

    const float* __restrict__ q_g = (br ? x2 : x1)
        + (size_t)bb * NSEQ * C_DIM + (size_t)qt * 128 * C_DIM + hh * HD;
    const __nv_bfloat16* __restrict__ KHg = g_kvh[1 - br];
    const __nv_bfloat16* __restrict__ KLg = g_kvl[1 - br];
    const __nv_bfloat16* __restrict__ VHg = g_kvh[br];
    const __nv_bfloat16* __restrict__ VLg = g_kvl[br];
    float* __restrict__ o_g = out + (size_t)br * NB * NSEQ * C_DIM
        + (size_t)bb * NSEQ * C_DIM + (size_t)qt * 128 * C_DIM + hh * HD;

    const int tid  = threadIdx.x;
    const int w    = tid >> 5;
    const int lane = tid & 31;
    const int g    = lane >> 2;
    const int tq   = lane & 3;

    const size_t kv_row0 = (size_t)bb * NSEQ;
    const int kcol = hh * HD;
    const int vcol = C_DIM + hh * HD;

    int cm[4], cd[4];
    #pragma unroll
    for (int l = 0; l < 4; l++) {
        const int c = tid + l * 256;
        cm[l] = c >> 3;
        cd[l] = (c & 7) * 8;
    }

    auto issue = [&](int mt, int p) {
        __nv_bfloat16* KH = smb + (2 + p * 4 + 0) * TILE_ELE;
        __nv_bfloat16* KL = smb + (2 + p * 4 + 1) * TILE_ELE;
        __nv_bfloat16* VH = smb + (2 + p * 4 + 2) * TILE_ELE;
        __nv_bfloat16* VL = smb + (2 + p * 4 + 3) * TILE_ELE;
        const size_t rbase = kv_row0 + (size_t)mt * 128;
        #pragma unroll
        for (int l = 0; l < 4; l++) {
            const size_t gidx = (rbase + cm[l]) * KVN;
            const int so = cm[l] * PAD + cd[l];
            cp16(smem_u32(&KH[so]), &KHg[gidx + kcol + cd[l]]);
            cp16(smem_u32(&KL[so]), &KLg[gidx + kcol + cd[l]]);
            cp16(smem_u32(&VH[so]), &VHg[gidx + vcol + cd[l]]);
            cp16(smem_u32(&VL[so]), &VLg[gidx + vcol + cd[l]]);
        }
        cp_commit();
    };

    issue(0, 0);
    #pragma unroll
    for (int l = 0; l < 8; l++) {
        const int c   = tid + l * 256;
        const int row = c >> 4;
        const int c4  = (c & 15) * 4;
        float4 q4 = *(const float4*)&q_g[(size_t)row * C_DIM + c4];
        q4.x *= SCALE; q4.y *= SCALE; q4.z *= SCALE; q4.w *= SCALE;
        uint32_t h0, l0, h1, l1;
        split2(q4.x, q4.y, h0, l0);
        split2(q4.z, q4.w, h1, l1);
        uint2 hv = {h0, h1}, lv = {l0, l1};
        *(uint2*)&QH[row * PAD + c4] = hv;
        *(uint2*)&QL[row * PAD + c4] = lv;
    }
    __syncthreads();

    const int a_row_off = (lane & 7) + ((lane >> 3) & 1) * 8;
    const int a_col_off = ((lane >> 4) & 1) * 8;
    uint32_t ah[16], al[16];
    #pragma unroll
    for (int ks = 0; ks < 4; ks++) {
        const int arow = w * 16 + a_row_off;
        const int acol = ks * 16 + a_col_off;
        ldsm_x4(&ah[ks * 4], smem_u32(&QH[arow * PAD + acol]));
        ldsm_x4(&al[ks * 4], smem_u32(&QL[arow * PAD + acol]));
    }

    float oacc[8][4] = {};
    const int b_quad = lane >> 3;
    const int b_r    = lane & 7;

    for (int mt = 0; mt < 8; mt++) {
        cp_wait0();
        __syncthreads();
        if (mt + 1 < 8) issue(mt + 1, (mt + 1) & 1);

        const int p = mt & 1;
        const __nv_bfloat16* KH = smb + (2 + p * 4 + 0) * TILE_ELE;
        const __nv_bfloat16* KL = smb + (2 + p * 4 + 1) * TILE_ELE;
        const __nv_bfloat16* VH = smb + (2 + p * 4 + 2) * TILE_ELE;
        const __nv_bfloat16* VL = smb + (2 + p * 4 + 3) * TILE_ELE;

        #pragma unroll
        for (int j = 0; j < 8; j++) {
            const int bcol  = b_quad * 8;
            const int brow0 = (2 * j + 0) * 8 + b_r;
            const int brow1 = (2 * j + 1) * 8 + b_r;
            uint32_t bh0[8], bl0[8], bh1[8], bl1[8];
            ldsm_x4(&bh0[0], smem_u32(&KH[brow0 * PAD + bcol]));
            ldsm_x4(&bh0[4], smem_u32(&KH[brow0 * PAD + 32 + bcol]));
            ldsm_x4(&bl0[0], smem_u32(&KL[brow0 * PAD + bcol]));
            ldsm_x4(&bl0[4], smem_u32(&KL[brow0 * PAD + 32 + bcol]));
            ldsm_x4(&bh1[0], smem_u32(&KH[brow1 * PAD + bcol]));
            ldsm_x4(&bh1[4], smem_u32(&KH[brow1 * PAD + 32 + bcol]));
            ldsm_x4(&bl1[0], smem_u32(&KL[brow1 * PAD + bcol]));
            ldsm_x4(&bl1[4], smem_u32(&KL[brow1 * PAD + 32 + bcol]));

            // ---- stage 1: 6 independent accumulator chains (4 mmas each) ----
            float s0h[4] = {}, s0m[4] = {}, s0l[4] = {};
            float s1h[4] = {}, s1m[4] = {}, s1l[4] = {};
            #pragma unroll
            for (int ks = 0; ks < 4; ks++) {
                mma16816(s0h, &ah[ks * 4], &bh0[ks * 2]);
                mma16816(s1h, &ah[ks * 4], &bh1[ks * 2]);
                mma16816(s0m, &ah[ks * 4], &bl0[ks * 2]);
                mma16816(s1m, &ah[ks * 4], &bl1[ks * 2]);
                mma16816(s0l, &al[ks * 4], &bh0[ks * 2]);
                mma16816(s1l, &al[ks * 4], &bh1[ks * 2]);
            }
            float s0[4], s1[4];
            #pragma unroll
            for (int r = 0; r < 4; r++) {
                s0[r] = (s0h[r] + s0m[r]) + s0l[r];
                s1[r] = (s1h[r] + s1m[r]) + s1l[r];
            }

            uint32_t sah[4], sal[4];
            split2(fmaxf(s0[0], 0.0f), fmaxf(s0[1], 0.0f), sah[0], sal[0]);
            split2(fmaxf(s0[2], 0.0f), fmaxf(s0[3], 0.0f), sah[1], sal[1]);
            split2(fmaxf(s1[0], 0.0f), fmaxf(s1[1], 0.0f), sah[2], sal[2]);
            split2(fmaxf(s1[2], 0.0f), fmaxf(s1[3], 0.0f), sah[3], sal[3]);

            // ---- stage 2: O += S . v (8 independent chains) ----
            const int vrow = j * 16 + (b_quad & 1) * 8 + b_r;
            #pragma unroll
            for (int np = 0; np < 4; np++) {
                const int col = np * 16 + (b_quad >> 1) * 8;
                uint32_t bvh[4], bvl[4];
                ldsm_x4t(bvh, smem_u32(&VH[vrow * PAD + col]));
                ldsm_x4t(bvl, smem_u32(&VL[vrow * PAD + col]));
                mma16816(oacc[2 * np],     sah, &bvh[0]);
                mma16816(oacc[2 * np + 1], sah, &bvh[2]);
                mma16816(oacc[2 * np],     sah, &bvl[0]);
                mma16816(oacc[2 * np + 1], sah, &bvl[2]);
                mma16816(oacc[2 * np],     sal, &bvh[0]);
                mma16816(oacc[2 * np + 1], sal, &bvh[2]);
            }
        }
        __syncthreads();
    }

    #pragma unroll
    for (int nt2 = 0; nt2 < 8; nt2++) {
        float2 v0 = {oacc[nt2][0], oacc[nt2][1]};
        float2 v1 = {oacc[nt2][2], oacc[nt2][3]};
        *(float2*)&o_g[(size_t)(w * 16 + g) * C_DIM + nt2 * 8 + 2 * tq] = v0;
        *(float2*)&o_g[(size_t)(w * 16 + g + 8) * C_DIM + nt2 * 8 + 2 * tq] = v1;
    }
}

// ---------------------------------------------------------------------------
extern "C" void kernel_launch(void* const* d_in, const int* in_sizes, int n_in,
                              void* d_out, int out_size) {
    const float* x1 = (const float*)d_in[0];
    const float* x2 = (const float*)d_in[1];
    const float* w1 = (const float*)d_in[2];
    const float* w2 = (const float*)d_in[3];
    float* out = (float*)d_out;

    (void)cudaFuncSetAttribute(attn_kernel,
                               cudaFuncAttributeMaxDynamicSharedMemorySize, ATTN_SMEM);
    (void)cudaFuncSetAttribute(kv_gemm,
                               cudaFuncAttributeMaxDynamicSharedMemorySize, KV_SMEM);

    __nv_bfloat16 *xh0, *xl0, *wh0, *wl0;
    (void)cudaGetSymbolAddress((void**)&xh0, g_xh);
    (void)cudaGetSymbolAddress((void**)&xl0, g_xl);
    (void)cudaGetSymbolAddress((void**)&wh0, g_wh);
    (void)cudaGetSymbolAddress((void**)&wl0, g_wl);

    split_all<<<(TOT4 + 255) / 256, 256>>>(x1, x2, w1, w2, xh0, xl0, wh0, wl0);

    dim3 g1(KVN / 128, M_TOT / 128, 2);
    kv_gemm<<<g1, 256, KV_SMEM>>>(0);

    dim3 g2(NSEQ / 128, NB * NHEADS, 2);
    attn_kernel<<<g2, 256, ATTN_SMEM>>>(x1, x2, out);
}

// round 10
// speedup vs baseline: 5.7372x; 1.3141x over previous
#include <cuda_runtime.h>
#include <cuda_fp16.h>
#include <cstdint>

constexpr int C_DIM  = 512;
constexpr int NHEADS = 8;
constexpr int HD     = 64;
constexpr int NB     = 8;
constexpr int NSEQ   = 1024;
constexpr int M_TOT  = NB * NSEQ;     // 8192
constexpr int KVN    = 2 * C_DIM;     // 1024
constexpr float SCALE = 0.125f;

// kv results as fp16 hi/lo planes
__device__ __half g_kvh[2][(size_t)M_TOT * KVN];
__device__ __half g_kvl[2][(size_t)M_TOT * KVN];
// pre-converted GEMM inputs: x needs hi only (A-operand); W needs hi+lo (B-operand)
__device__ __half g_xh[2][(size_t)M_TOT * C_DIM];
__device__ __half g_wh[2][(size_t)C_DIM * KVN];
__device__ __half g_wl[2][(size_t)C_DIM * KVN];

// ---------------------------------------------------------------------------
__device__ __forceinline__ uint32_t smem_u32(const void* p) {
    return (uint32_t)__cvta_generic_to_shared(p);
}
__device__ __forceinline__ void ldsm_x4(uint32_t* r, uint32_t a) {
    asm volatile("ldmatrix.sync.aligned.m8n8.x4.shared.b16 {%0,%1,%2,%3}, [%4];"
                 : "=r"(r[0]), "=r"(r[1]), "=r"(r[2]), "=r"(r[3]) : "r"(a));
}
__device__ __forceinline__ void ldsm_x4t(uint32_t* r, uint32_t a) {
    asm volatile("ldmatrix.sync.aligned.m8n8.x4.trans.shared.b16 {%0,%1,%2,%3}, [%4];"
                 : "=r"(r[0]), "=r"(r[1]), "=r"(r[2]), "=r"(r[3]) : "r"(a));
}
__device__ __forceinline__ void mmaH(float* c, const uint32_t* a, const uint32_t* b) {
    asm volatile("mma.sync.aligned.m16n8k16.row.col.f32.f16.f16.f32 "
                 "{%0,%1,%2,%3}, {%4,%5,%6,%7}, {%8,%9}, {%0,%1,%2,%3};"
                 : "+f"(c[0]), "+f"(c[1]), "+f"(c[2]), "+f"(c[3])
                 : "r"(a[0]), "r"(a[1]), "r"(a[2]), "r"(a[3]), "r"(b[0]), "r"(b[1]));
}
// round fp32 pair to one packed fp16x2 word
__device__ __forceinline__ uint32_t packH(float x0, float x1) {
    __half2 h = __floats2half2_rn(x0, x1);
    return *reinterpret_cast<uint32_t*>(&h);
}
// split fp32 pair into fp16 hi + fp16 residual planes
__device__ __forceinline__ void splitH(float x0, float x1, uint32_t& hi, uint32_t& lo) {
    __half h0 = __float2half_rn(x0);
    __half h1 = __float2half_rn(x1);
    __half2 hp; hp.x = h0; hp.y = h1;
    __half2 lp;
    lp.x = __float2half_rn(x0 - __half2float(h0));
    lp.y = __float2half_rn(x1 - __half2float(h1));
    hi = *reinterpret_cast<uint32_t*>(&hp);
    lo = *reinterpret_cast<uint32_t*>(&lp);
}
__device__ __forceinline__ void cp16(uint32_t s, const void* g) {
    asm volatile("cp.async.cg.shared.global [%0], [%1], 16;" :: "r"(s), "l"(g));
}
__device__ __forceinline__ void cp_commit() { asm volatile("cp.async.commit_group;"); }
__device__ __forceinline__ void cp_wait0()  { asm volatile("cp.async.wait_group 0;"); }

// ---------------------------------------------------------------------------
// Kernel 0: convert inputs. x1/x2 -> fp16 hi only; w1/w2 -> fp16 hi+lo.
// ---------------------------------------------------------------------------
constexpr int XN4 = M_TOT * C_DIM / 4;    // 1,048,576
constexpr int WN4 = C_DIM * KVN / 4;      // 131,072
constexpr int TOT4 = 2 * XN4 + 2 * WN4;

__global__ __launch_bounds__(256) void split_all(const float* __restrict__ x1,
                                                 const float* __restrict__ x2,
                                                 const float* __restrict__ w1,
                                                 const float* __restrict__ w2,
                                                 __half* __restrict__ xh,
                                                 __half* __restrict__ wh,
                                                 __half* __restrict__ wl) {
    const int i = blockIdx.x * blockDim.x + threadIdx.x;
    if (i >= TOT4) return;
    if (i < 2 * XN4) {
        const float* s = (i < XN4) ? x1 : x2;
        const size_t off = (i < XN4) ? (size_t)i : (size_t)(i - XN4);
        __half* dh = xh + ((i < XN4) ? 0 : (size_t)M_TOT * C_DIM);
        const float4 v = *(const float4*)&s[off * 4];
        uint2 hv = {packH(v.x, v.y), packH(v.z, v.w)};
        *(uint2*)&dh[off * 4] = hv;
    } else {
        const int j = i - 2 * XN4;
        const float* s = (j < WN4) ? w1 : w2;
        const size_t off = (j < WN4) ? (size_t)j : (size_t)(j - WN4);
        const size_t pb = (j < WN4) ? 0 : (size_t)C_DIM * KVN;
        const float4 v = *(const float4*)&s[off * 4];
        uint32_t h0, l0, h1, l1;
        splitH(v.x, v.y, h0, l0);
        splitH(v.z, v.w, h1, l1);
        uint2 hv = {h0, h1}, lv = {l0, l1};
        *(uint2*)&wh[pb + off * 4] = hv;
        *(uint2*)&wl[pb + off * 4] = lv;
    }
}

// ---------------------------------------------------------------------------
// Kernel 1: kv = x @ W.  A = xh (1 plane), B = {wh, wl} -> 2 products.
// 128x128 CTA tile, K-step 32, warp tile 64x32, cp.async 2-stage.
// ---------------------------------------------------------------------------
constexpr int XPAD = 40;
constexpr int WPAD = 136;
constexpr int XT = 128 * XPAD;         // 5120
constexpr int WT = 32 * WPAD;          // 4352
constexpr int KV_SMEM = (2 * XT + 4 * WT) * 2;   // 55296 B

__global__ __launch_bounds__(256, 1) void kv_gemm(int dummy) {
    extern __shared__ __half ksm[];
    const int br = blockIdx.z;
    const __half* __restrict__ XH_g = g_xh[br];
    const __half* __restrict__ WH_g = g_wh[br];
    const __half* __restrict__ WL_g = g_wl[br];
    __half* __restrict__ Oh = g_kvh[br];
    __half* __restrict__ Ol = g_kvl[br];

    const int t    = threadIdx.x;
    const int w    = t >> 5;
    const int lane = t & 31;
    const int g    = lane >> 2;
    const int tq   = lane & 3;
    const int wm   = w >> 2;
    const int wn   = w & 3;
    const int m0   = blockIdx.y * 128;
    const int n0   = blockIdx.x * 128;

    const int a_row = wm * 64 + (lane & 7) + ((lane >> 3) & 1) * 8;
    const int a_col = ((lane >> 4) & 1) * 8;
    const int b_quad = lane >> 3;
    const int b_r    = lane & 7;

    const int xr0 = (t + 0)   >> 2, xc0 = ((t + 0)   & 3) * 8;
    const int xr1 = (t + 256) >> 2, xc1 = ((t + 256) & 3) * 8;
    const int wr0 = (t + 0)   >> 4, wc0 = ((t + 0)   & 15) * 8;
    const int wr1 = (t + 256) >> 4, wc1 = ((t + 256) & 15) * 8;

    auto issue = [&](int k0, int p) {
        __half* XH = ksm + p * XT;
        __half* WH = ksm + 2 * XT + p * WT;
        __half* WL = ksm + 2 * XT + 2 * WT + p * WT;
        cp16(smem_u32(&XH[xr0 * XPAD + xc0]), &XH_g[(size_t)(m0 + xr0) * C_DIM + k0 + xc0]);
        cp16(smem_u32(&XH[xr1 * XPAD + xc1]), &XH_g[(size_t)(m0 + xr1) * C_DIM + k0 + xc1]);
        cp16(smem_u32(&WH[wr0 * WPAD + wc0]), &WH_g[(size_t)(k0 + wr0) * KVN + n0 + wc0]);
        cp16(smem_u32(&WH[wr1 * WPAD + wc1]), &WH_g[(size_t)(k0 + wr1) * KVN + n0 + wc1]);
        cp16(smem_u32(&WL[wr0 * WPAD + wc0]), &WL_g[(size_t)(k0 + wr0) * KVN + n0 + wc0]);
        cp16(smem_u32(&WL[wr1 * WPAD + wc1]), &WL_g[(size_t)(k0 + wr1) * KVN + n0 + wc1]);
        cp_commit();
    };

    float acc[4][4][4] = {};

    issue(0, 0);
    for (int ki = 0; ki < 16; ki++) {
        cp_wait0();
        __syncthreads();
        if (ki + 1 < 16) issue((ki + 1) * 32, (ki + 1) & 1);
        const int p = ki & 1;
        const __half* XH = ksm + p * XT;
        const __half* WH = ksm + 2 * XT + p * WT;
        const __half* WL = ksm + 2 * XT + 2 * WT + p * WT;

        #pragma unroll
        for (int ks = 0; ks < 2; ks++) {
            uint32_t ah[4][4];
            #pragma unroll
            for (int mi = 0; mi < 4; mi++) {
                const int addr = (a_row + mi * 16) * XPAD + ks * 16 + a_col;
                ldsm_x4(ah[mi], smem_u32(&XH[addr]));
            }
            uint32_t bh[2][4], bl[2][4];
            #pragma unroll
            for (int nip = 0; nip < 2; nip++) {
                const int row = ks * 16 + (b_quad & 1) * 8 + b_r;
                const int col = wn * 32 + nip * 16 + (b_quad >> 1) * 8;
                ldsm_x4t(bh[nip], smem_u32(&WH[row * WPAD + col]));
                ldsm_x4t(bl[nip], smem_u32(&WL[row * WPAD + col]));
            }
            #pragma unroll
            for (int mi = 0; mi < 4; mi++)
                #pragma unroll
                for (int nn = 0; nn < 4; nn++) {
                    const uint32_t* bhp = &bh[nn >> 1][(nn & 1) * 2];
                    const uint32_t* blp = &bl[nn >> 1][(nn & 1) * 2];
                    mmaH(acc[mi][nn], ah[mi], bhp);
                    mmaH(acc[mi][nn], ah[mi], blp);
                }
        }
        __syncthreads();
    }

    #pragma unroll
    for (int mi = 0; mi < 4; mi++)
        #pragma unroll
        for (int nn = 0; nn < 4; nn++) {
            const int row = m0 + wm * 64 + mi * 16 + g;
            const int col = n0 + wn * 32 + nn * 8 + 2 * tq;
            uint32_t hi, lo;
            splitH(acc[mi][nn][0], acc[mi][nn][1], hi, lo);
            *(uint32_t*)&Oh[(size_t)row * KVN + col] = hi;
            *(uint32_t*)&Ol[(size_t)row * KVN + col] = lo;
            splitH(acc[mi][nn][2], acc[mi][nn][3], hi, lo);
            *(uint32_t*)&Oh[(size_t)(row + 8) * KVN + col] = hi;
            *(uint32_t*)&Ol[(size_t)(row + 8) * KVN + col] = lo;
        }
}

// ---------------------------------------------------------------------------
// Kernel 2: fused cross attention (fp16, 2-product).
// A-operands 1 plane (QH, SH); B-operands 2 planes (K, V hi+lo).
// smem: QH + 2 x (KH KL VH VL) = 9 planes of 128x88 fp16 = 202752 B.
// ---------------------------------------------------------------------------
constexpr int PAD = 88;
constexpr int TILE_ELE = 128 * PAD;
constexpr int ATTN_SMEM = 9 * TILE_ELE * 2;   // 202752 B

__global__ __launch_bounds__(256, 1) void attn_kernel(const float* __restrict__ x1,
                                                      const float* __restrict__ x2,
                                                      float* __restrict__ out) {
    extern __shared__ __half smb[];
    __half* QH = smb;

    const int br = blockIdx.z;
    const int bh = blockIdx.y;
    const int bb = bh >> 3;
    const int hh = bh & 7;
    const int qt = blockIdx.x;

    const float* __restrict__ q_g = (br ? x2 : x1)
        + (size_t)bb * NSEQ * C_DIM + (size_t)qt * 128 * C_DIM + hh * HD;
    const __half* __restrict__ KHg = g_kvh[1 - br];
    const __half* __restrict__ KLg = g_kvl[1 - br];
    const __half* __restrict__ VHg = g_kvh[br];
    const __half* __restrict__ VLg = g_kvl[br];
    float* __restrict__ o_g = out + (size_t)br * NB * NSEQ * C_DIM
        + (size_t)bb * NSEQ * C_DIM + (size_t)qt * 128 * C_DIM + hh * HD;

    const int tid  = threadIdx.x;
    const int w    = tid >> 5;
    const int lane = tid & 31;
    const int g    = lane >> 2;
    const int tq   = lane & 3;

    const size_t kv_row0 = (size_t)bb * NSEQ;
    const int kcol = hh * HD;
    const int vcol = C_DIM + hh * HD;

    int cm[4], cd[4];
    #pragma unroll
    for (int l = 0; l < 4; l++) {
        const int c = tid + l * 256;
        cm[l] = c >> 3;
        cd[l] = (c & 7) * 8;
    }

    auto issue = [&](int mt, int p) {
        __half* KH = smb + (1 + p * 4 + 0) * TILE_ELE;
        __half* KL = smb + (1 + p * 4 + 1) * TILE_ELE;
        __half* VH = smb + (1 + p * 4 + 2) * TILE_ELE;
        __half* VL = smb + (1 + p * 4 + 3) * TILE_ELE;
        const size_t rbase = kv_row0 + (size_t)mt * 128;
        #pragma unroll
        for (int l = 0; l < 4; l++) {
            const size_t gidx = (rbase + cm[l]) * KVN;
            const int so = cm[l] * PAD + cd[l];
            cp16(smem_u32(&KH[so]), &KHg[gidx + kcol + cd[l]]);
            cp16(smem_u32(&KL[so]), &KLg[gidx + kcol + cd[l]]);
            cp16(smem_u32(&VH[so]), &VHg[gidx + vcol + cd[l]]);
            cp16(smem_u32(&VL[so]), &VLg[gidx + vcol + cd[l]]);
        }
        cp_commit();
    };

    // ---- prologue: issue tile 0; load + scale + round Q to fp16 ----
    issue(0, 0);
    #pragma unroll
    for (int l = 0; l < 8; l++) {
        const int c   = tid + l * 256;
        const int row = c >> 4;
        const int c4  = (c & 15) * 4;
        float4 q4 = *(const float4*)&q_g[(size_t)row * C_DIM + c4];
        uint2 hv = {packH(q4.x * SCALE, q4.y * SCALE), packH(q4.z * SCALE, q4.w * SCALE)};
        *(uint2*)&QH[row * PAD + c4] = hv;
    }
    __syncthreads();

    // loop-invariant Q fragments
    const int a_row_off = (lane & 7) + ((lane >> 3) & 1) * 8;
    const int a_col_off = ((lane >> 4) & 1) * 8;
    uint32_t ah[16];
    #pragma unroll
    for (int ks = 0; ks < 4; ks++) {
        const int arow = w * 16 + a_row_off;
        const int acol = ks * 16 + a_col_off;
        ldsm_x4(&ah[ks * 4], smem_u32(&QH[arow * PAD + acol]));
    }

    float oacc[8][4] = {};
    const int b_quad = lane >> 3;
    const int b_r    = lane & 7;

    for (int mt = 0; mt < 8; mt++) {
        cp_wait0();
        __syncthreads();
        if (mt + 1 < 8) issue(mt + 1, (mt + 1) & 1);

        const int p = mt & 1;
        const __half* KH = smb + (1 + p * 4 + 0) * TILE_ELE;
        const __half* KL = smb + (1 + p * 4 + 1) * TILE_ELE;
        const __half* VH = smb + (1 + p * 4 + 2) * TILE_ELE;
        const __half* VL = smb + (1 + p * 4 + 3) * TILE_ELE;

        #pragma unroll
        for (int j = 0; j < 8; j++) {
            const int bcol  = b_quad * 8;
            const int brow0 = (2 * j + 0) * 8 + b_r;
            const int brow1 = (2 * j + 1) * 8 + b_r;
            uint32_t bh0[8], bl0[8], bh1[8], bl1[8];
            ldsm_x4(&bh0[0], smem_u32(&KH[brow0 * PAD + bcol]));
            ldsm_x4(&bh0[4], smem_u32(&KH[brow0 * PAD + 32 + bcol]));
            ldsm_x4(&bl0[0], smem_u32(&KL[brow0 * PAD + bcol]));
            ldsm_x4(&bl0[4], smem_u32(&KL[brow0 * PAD + 32 + bcol]));
            ldsm_x4(&bh1[0], smem_u32(&KH[brow1 * PAD + bcol]));
            ldsm_x4(&bh1[4], smem_u32(&KH[brow1 * PAD + 32 + bcol]));
            ldsm_x4(&bl1[0], smem_u32(&KL[brow1 * PAD + bcol]));
            ldsm_x4(&bl1[4], smem_u32(&KL[brow1 * PAD + 32 + bcol]));

            // ---- stage 1: 4 independent chains (ah x {bh,bl} x {half0,half1}) ----
            float s0a[4] = {}, s0b[4] = {}, s1a[4] = {}, s1b[4] = {};
            #pragma unroll
            for (int ks = 0; ks < 4; ks++) {
                mmaH(s0a, &ah[ks * 4], &bh0[ks * 2]);
                mmaH(s1a, &ah[ks * 4], &bh1[ks * 2]);
                mmaH(s0b, &ah[ks * 4], &bl0[ks * 2]);
                mmaH(s1b, &ah[ks * 4], &bl1[ks * 2]);
            }
            float s0[4], s1[4];
            #pragma unroll
            for (int r = 0; r < 4; r++) {
                s0[r] = s0a[r] + s0b[r];
                s1[r] = s1a[r] + s1b[r];
            }

            // relu (scale folded into q), round S to fp16 A-fragment (1 plane)
            uint32_t sah[4];
            sah[0] = packH(fmaxf(s0[0], 0.0f), fmaxf(s0[1], 0.0f));
            sah[1] = packH(fmaxf(s0[2], 0.0f), fmaxf(s0[3], 0.0f));
            sah[2] = packH(fmaxf(s1[0], 0.0f), fmaxf(s1[1], 0.0f));
            sah[3] = packH(fmaxf(s1[2], 0.0f), fmaxf(s1[3], 0.0f));

            // ---- stage 2: O += S . v  (8 chains, 2 products) ----
            const int vrow = j * 16 + (b_quad & 1) * 8 + b_r;
            #pragma unroll
            for (int np = 0; np < 4; np++) {
                const int col = np * 16 + (b_quad >> 1) * 8;
                uint32_t bvh[4], bvl[4];
                ldsm_x4t(bvh, smem_u32(&VH[vrow * PAD + col]));
                ldsm_x4t(bvl, smem_u32(&VL[vrow * PAD + col]));
                mmaH(oacc[2 * np],     sah, &bvh[0]);
                mmaH(oacc[2 * np + 1], sah, &bvh[2]);
                mmaH(oacc[2 * np],     sah, &bvl[0]);
                mmaH(oacc[2 * np + 1], sah, &bvl[2]);
            }
        }
        __syncthreads();
    }

    #pragma unroll
    for (int nt2 = 0; nt2 < 8; nt2++) {
        float2 v0 = {oacc[nt2][0], oacc[nt2][1]};
        float2 v1 = {oacc[nt2][2], oacc[nt2][3]};
        *(float2*)&o_g[(size_t)(w * 16 + g) * C_DIM + nt2 * 8 + 2 * tq] = v0;
        *(float2*)&o_g[(size_t)(w * 16 + g + 8) * C_DIM + nt2 * 8 + 2 * tq] = v1;
    }
}

// ---------------------------------------------------------------------------
extern "C" void kernel_launch(void* const* d_in, const int* in_sizes, int n_in,
                              void* d_out, int out_size) {
    const float* x1 = (const float*)d_in[0];
    const float* x2 = (const float*)d_in[1];
    const float* w1 = (const float*)d_in[2];
    const float* w2 = (const float*)d_in[3];
    float* out = (float*)d_out;

    (void)cudaFuncSetAttribute(attn_kernel,
                               cudaFuncAttributeMaxDynamicSharedMemorySize, ATTN_SMEM);
    (void)cudaFuncSetAttribute(kv_gemm,
                               cudaFuncAttributeMaxDynamicSharedMemorySize, KV_SMEM);

    __half *xh0, *wh0, *wl0;
    (void)cudaGetSymbolAddress((void**)&xh0, g_xh);
    (void)cudaGetSymbolAddress((void**)&wh0, g_wh);
    (void)cudaGetSymbolAddress((void**)&wl0, g_wl);

    split_all<<<(TOT4 + 255) / 256, 256>>>(x1, x2, w1, w2, xh0, wh0, wl0);

    dim3 g1(KVN / 128, M_TOT / 128, 2);
    kv_gemm<<<g1, 256, KV_SMEM>>>(0);

    dim3 g2(NSEQ / 128, NB * NHEADS, 2);
    attn_kernel<<<g2, 256, ATTN_SMEM>>>(x1, x2, out);
}

// round 11
// speedup vs baseline: 10.5563x; 1.8400x over previous
#include <cuda_runtime.h>
#include <cuda_fp16.h>
#include <cstdint>

constexpr int C_DIM  = 512;
constexpr int NHEADS = 8;
constexpr int HD     = 64;
constexpr int NB     = 8;
constexpr int NSEQ   = 1024;
constexpr int M_TOT  = NB * NSEQ;     // 8192
constexpr int KVN    = 2 * C_DIM;     // 1024
constexpr float SCALE = 0.125f;

// fp16 planes: kv result, converted inputs
__device__ __half g_kvh[2][(size_t)M_TOT * KVN];
__device__ __half g_xh[2][(size_t)M_TOT * C_DIM];
__device__ __half g_wh[2][(size_t)C_DIM * KVN];

// ---------------------------------------------------------------------------
__device__ __forceinline__ uint32_t smem_u32(const void* p) {
    return (uint32_t)__cvta_generic_to_shared(p);
}
__device__ __forceinline__ void ldsm_x4(uint32_t* r, uint32_t a) {
    asm volatile("ldmatrix.sync.aligned.m8n8.x4.shared.b16 {%0,%1,%2,%3}, [%4];"
                 : "=r"(r[0]), "=r"(r[1]), "=r"(r[2]), "=r"(r[3]) : "r"(a));
}
__device__ __forceinline__ void ldsm_x4t(uint32_t* r, uint32_t a) {
    asm volatile("ldmatrix.sync.aligned.m8n8.x4.trans.shared.b16 {%0,%1,%2,%3}, [%4];"
                 : "=r"(r[0]), "=r"(r[1]), "=r"(r[2]), "=r"(r[3]) : "r"(a));
}
__device__ __forceinline__ void mmaH(float* c, const uint32_t* a, const uint32_t* b) {
    asm volatile("mma.sync.aligned.m16n8k16.row.col.f32.f16.f16.f32 "
                 "{%0,%1,%2,%3}, {%4,%5,%6,%7}, {%8,%9}, {%0,%1,%2,%3};"
                 : "+f"(c[0]), "+f"(c[1]), "+f"(c[2]), "+f"(c[3])
                 : "r"(a[0]), "r"(a[1]), "r"(a[2]), "r"(a[3]), "r"(b[0]), "r"(b[1]));
}
__device__ __forceinline__ uint32_t packH(float x0, float x1) {
    __half2 h = __floats2half2_rn(x0, x1);
    return *reinterpret_cast<uint32_t*>(&h);
}
__device__ __forceinline__ void cp16(uint32_t s, const void* g) {
    asm volatile("cp.async.cg.shared.global [%0], [%1], 16;" :: "r"(s), "l"(g));
}
__device__ __forceinline__ void cp_commit() { asm volatile("cp.async.commit_group;"); }
__device__ __forceinline__ void cp_wait0()  { asm volatile("cp.async.wait_group 0;"); }

// ---------------------------------------------------------------------------
// Kernel 0: convert x1/x2/w1/w2 -> fp16 planes.
// ---------------------------------------------------------------------------
constexpr int XN4 = M_TOT * C_DIM / 4;
constexpr int WN4 = C_DIM * KVN / 4;
constexpr int TOT4 = 2 * XN4 + 2 * WN4;

__global__ __launch_bounds__(256) void split_all(const float* __restrict__ x1,
                                                 const float* __restrict__ x2,
                                                 const float* __restrict__ w1,
                                                 const float* __restrict__ w2,
                                                 __half* __restrict__ xh,
                                                 __half* __restrict__ wh) {
    const int i = blockIdx.x * blockDim.x + threadIdx.x;
    if (i >= TOT4) return;
    const float* s;
    __half* d;
    size_t off;
    if (i < XN4)                { s = x1; d = xh;                                off = i; }
    else if (i < 2 * XN4)       { s = x2; d = xh + (size_t)M_TOT * C_DIM;        off = i - XN4; }
    else if (i < 2 * XN4 + WN4) { s = w1; d = wh;                                off = i - 2 * XN4; }
    else                        { s = w2; d = wh + (size_t)C_DIM * KVN;          off = i - 2 * XN4 - WN4; }
    const float4 v = *(const float4*)&s[off * 4];
    uint2 hv = {packH(v.x, v.y), packH(v.z, v.w)};
    *(uint2*)&d[off * 4] = hv;
}

// ---------------------------------------------------------------------------
// Kernel 1: kv = x @ W, pure fp16, 1 product.
// 128x128 CTA tile, K-step 32, warp tile 64x32, cp.async 2-stage.
// ---------------------------------------------------------------------------
constexpr int XPAD = 40;
constexpr int WPAD = 136;
constexpr int XT = 128 * XPAD;         // 5120
constexpr int WT = 32 * WPAD;          // 4352
constexpr int KV_SMEM = (2 * XT + 2 * WT) * 2;   // 37888 B

__global__ __launch_bounds__(256, 1) void kv_gemm(int dummy) {
    extern __shared__ __half ksm[];
    const int br = blockIdx.z;
    const __half* __restrict__ XH_g = g_xh[br];
    const __half* __restrict__ WH_g = g_wh[br];
    __half* __restrict__ Oh = g_kvh[br];

    const int t    = threadIdx.x;
    const int w    = t >> 5;
    const int lane = t & 31;
    const int g    = lane >> 2;
    const int tq   = lane & 3;
    const int wm   = w >> 2;
    const int wn   = w & 3;
    const int m0   = blockIdx.y * 128;
    const int n0   = blockIdx.x * 128;

    const int a_row = wm * 64 + (lane & 7) + ((lane >> 3) & 1) * 8;
    const int a_col = ((lane >> 4) & 1) * 8;
    const int b_quad = lane >> 3;
    const int b_r    = lane & 7;

    const int xr0 = (t + 0)   >> 2, xc0 = ((t + 0)   & 3) * 8;
    const int xr1 = (t + 256) >> 2, xc1 = ((t + 256) & 3) * 8;
    const int wr0 = (t + 0)   >> 4, wc0 = ((t + 0)   & 15) * 8;
    const int wr1 = (t + 256) >> 4, wc1 = ((t + 256) & 15) * 8;

    auto issue = [&](int k0, int p) {
        __half* XH = ksm + p * XT;
        __half* WH = ksm + 2 * XT + p * WT;
        cp16(smem_u32(&XH[xr0 * XPAD + xc0]), &XH_g[(size_t)(m0 + xr0) * C_DIM + k0 + xc0]);
        cp16(smem_u32(&XH[xr1 * XPAD + xc1]), &XH_g[(size_t)(m0 + xr1) * C_DIM + k0 + xc1]);
        cp16(smem_u32(&WH[wr0 * WPAD + wc0]), &WH_g[(size_t)(k0 + wr0) * KVN + n0 + wc0]);
        cp16(smem_u32(&WH[wr1 * WPAD + wc1]), &WH_g[(size_t)(k0 + wr1) * KVN + n0 + wc1]);
        cp_commit();
    };

    float acc[4][4][4] = {};

    issue(0, 0);
    for (int ki = 0; ki < 16; ki++) {
        cp_wait0();
        __syncthreads();
        if (ki + 1 < 16) issue((ki + 1) * 32, (ki + 1) & 1);
        const int p = ki & 1;
        const __half* XH = ksm + p * XT;
        const __half* WH = ksm + 2 * XT + p * WT;

        #pragma unroll
        for (int ks = 0; ks < 2; ks++) {
            uint32_t ah[4][4];
            #pragma unroll
            for (int mi = 0; mi < 4; mi++) {
                const int addr = (a_row + mi * 16) * XPAD + ks * 16 + a_col;
                ldsm_x4(ah[mi], smem_u32(&XH[addr]));
            }
            uint32_t bh[2][4];
            #pragma unroll
            for (int nip = 0; nip < 2; nip++) {
                const int row = ks * 16 + (b_quad & 1) * 8 + b_r;
                const int col = wn * 32 + nip * 16 + (b_quad >> 1) * 8;
                ldsm_x4t(bh[nip], smem_u32(&WH[row * WPAD + col]));
            }
            #pragma unroll
            for (int mi = 0; mi < 4; mi++)
                #pragma unroll
                for (int nn = 0; nn < 4; nn++)
                    mmaH(acc[mi][nn], ah[mi], &bh[nn >> 1][(nn & 1) * 2]);
        }
        __syncthreads();
    }

    #pragma unroll
    for (int mi = 0; mi < 4; mi++)
        #pragma unroll
        for (int nn = 0; nn < 4; nn++) {
            const int row = m0 + wm * 64 + mi * 16 + g;
            const int col = n0 + wn * 32 + nn * 8 + 2 * tq;
            *(uint32_t*)&Oh[(size_t)row * KVN + col] = packH(acc[mi][nn][0], acc[mi][nn][1]);
            *(uint32_t*)&Oh[(size_t)(row + 8) * KVN + col] = packH(acc[mi][nn][2], acc[mi][nn][3]);
        }
}

// ---------------------------------------------------------------------------
// Kernel 2: fused cross attention, pure fp16 (1 product per GEMM stage).
// smem: QH + 2 x (KH, VH) = 5 planes of 128x88 fp16 = 112640 B -> 2 CTAs/SM.
// ---------------------------------------------------------------------------
constexpr int PAD = 88;
constexpr int TILE_ELE = 128 * PAD;
constexpr int ATTN_SMEM = 5 * TILE_ELE * 2;   // 112640 B

__global__ __launch_bounds__(256, 2) void attn_kernel(const float* __restrict__ x1,
                                                      const float* __restrict__ x2,
                                                      float* __restrict__ out) {
    extern __shared__ __half smb[];
    __half* QH = smb;

    const int br = blockIdx.z;
    const int bh = blockIdx.y;
    const int bb = bh >> 3;
    const int hh = bh & 7;
    const int qt = blockIdx.x;

    const float* __restrict__ q_g = (br ? x2 : x1)
        + (size_t)bb * NSEQ * C_DIM + (size_t)qt * 128 * C_DIM + hh * HD;
    const __half* __restrict__ KHg = g_kvh[1 - br];
    const __half* __restrict__ VHg = g_kvh[br];
    float* __restrict__ o_g = out + (size_t)br * NB * NSEQ * C_DIM
        + (size_t)bb * NSEQ * C_DIM + (size_t)qt * 128 * C_DIM + hh * HD;

    const int tid  = threadIdx.x;
    const int w    = tid >> 5;
    const int lane = tid & 31;
    const int g    = lane >> 2;
    const int tq   = lane & 3;

    const size_t kv_row0 = (size_t)bb * NSEQ;
    const int kcol = hh * HD;
    const int vcol = C_DIM + hh * HD;

    int cm[4], cd[4];
    #pragma unroll
    for (int l = 0; l < 4; l++) {
        const int c = tid + l * 256;
        cm[l] = c >> 3;
        cd[l] = (c & 7) * 8;
    }

    auto issue = [&](int mt, int p) {
        __half* KH = smb + (1 + p * 2 + 0) * TILE_ELE;
        __half* VH = smb + (1 + p * 2 + 1) * TILE_ELE;
        const size_t rbase = kv_row0 + (size_t)mt * 128;
        #pragma unroll
        for (int l = 0; l < 4; l++) {
            const size_t gidx = (rbase + cm[l]) * KVN;
            const int so = cm[l] * PAD + cd[l];
            cp16(smem_u32(&KH[so]), &KHg[gidx + kcol + cd[l]]);
            cp16(smem_u32(&VH[so]), &VHg[gidx + vcol + cd[l]]);
        }
        cp_commit();
    };

    // ---- prologue: issue tile 0; load + scale + round Q to fp16 ----
    issue(0, 0);
    #pragma unroll
    for (int l = 0; l < 8; l++) {
        const int c   = tid + l * 256;
        const int row = c >> 4;
        const int c4  = (c & 15) * 4;
        float4 q4 = *(const float4*)&q_g[(size_t)row * C_DIM + c4];
        uint2 hv = {packH(q4.x * SCALE, q4.y * SCALE), packH(q4.z * SCALE, q4.w * SCALE)};
        *(uint2*)&QH[row * PAD + c4] = hv;
    }
    __syncthreads();

    // loop-invariant Q fragments
    const int a_row_off = (lane & 7) + ((lane >> 3) & 1) * 8;
    const int a_col_off = ((lane >> 4) & 1) * 8;
    uint32_t ah[16];
    #pragma unroll
    for (int ks = 0; ks < 4; ks++) {
        const int arow = w * 16 + a_row_off;
        const int acol = ks * 16 + a_col_off;
        ldsm_x4(&ah[ks * 4], smem_u32(&QH[arow * PAD + acol]));
    }

    float oacc[8][4] = {};
    const int b_quad = lane >> 3;
    const int b_r    = lane & 7;

    for (int mt = 0; mt < 8; mt++) {
        cp_wait0();
        __syncthreads();
        if (mt + 1 < 8) issue(mt + 1, (mt + 1) & 1);

        const int p = mt & 1;
        const __half* KH = smb + (1 + p * 2 + 0) * TILE_ELE;
        const __half* VH = smb + (1 + p * 2 + 1) * TILE_ELE;

        #pragma unroll
        for (int j = 0; j < 8; j++) {
            const int bcol  = b_quad * 8;
            const int brow0 = (2 * j + 0) * 8 + b_r;
            const int brow1 = (2 * j + 1) * 8 + b_r;
            uint32_t bh0[8], bh1[8];
            ldsm_x4(&bh0[0], smem_u32(&KH[brow0 * PAD + bcol]));
            ldsm_x4(&bh0[4], smem_u32(&KH[brow0 * PAD + 32 + bcol]));
            ldsm_x4(&bh1[0], smem_u32(&KH[brow1 * PAD + bcol]));
            ldsm_x4(&bh1[4], smem_u32(&KH[brow1 * PAD + 32 + bcol]));

            // ---- stage 1: 4 independent chains (2 halves x 2 k-splits) ----
            float s0a[4] = {}, s0b[4] = {}, s1a[4] = {}, s1b[4] = {};
            #pragma unroll
            for (int ks = 0; ks < 2; ks++) {
                mmaH(s0a, &ah[ks * 4], &bh0[ks * 2]);
                mmaH(s1a, &ah[ks * 4], &bh1[ks * 2]);
                mmaH(s0b, &ah[(ks + 2) * 4], &bh0[(ks + 2) * 2]);
                mmaH(s1b, &ah[(ks + 2) * 4], &bh1[(ks + 2) * 2]);
            }

            // relu (scale folded into q), round S to fp16 A-fragment
            uint32_t sah[4];
            sah[0] = packH(fmaxf(s0a[0] + s0b[0], 0.0f), fmaxf(s0a[1] + s0b[1], 0.0f));
            sah[1] = packH(fmaxf(s0a[2] + s0b[2], 0.0f), fmaxf(s0a[3] + s0b[3], 0.0f));
            sah[2] = packH(fmaxf(s1a[0] + s1b[0], 0.0f), fmaxf(s1a[1] + s1b[1], 0.0f));
            sah[3] = packH(fmaxf(s1a[2] + s1b[2], 0.0f), fmaxf(s1a[3] + s1b[3], 0.0f));

            // ---- stage 2: O += S . v  (8 independent accumulators) ----
            const int vrow = j * 16 + (b_quad & 1) * 8 + b_r;
            #pragma unroll
            for (int np = 0; np < 4; np++) {
                const int col = np * 16 + (b_quad >> 1) * 8;
                uint32_t bvh[4];
                ldsm_x4t(bvh, smem_u32(&VH[vrow * PAD + col]));
                mmaH(oacc[2 * np],     sah, &bvh[0]);
                mmaH(oacc[2 * np + 1], sah, &bvh[2]);
            }
        }
        __syncthreads();
    }

    #pragma unroll
    for (int nt2 = 0; nt2 < 8; nt2++) {
        float2 v0 = {oacc[nt2][0], oacc[nt2][1]};
        float2 v1 = {oacc[nt2][2], oacc[nt2][3]};
        *(float2*)&o_g[(size_t)(w * 16 + g) * C_DIM + nt2 * 8 + 2 * tq] = v0;
        *(float2*)&o_g[(size_t)(w * 16 + g + 8) * C_DIM + nt2 * 8 + 2 * tq] = v1;
    }
}

// ---------------------------------------------------------------------------
extern "C" void kernel_launch(void* const* d_in, const int* in_sizes, int n_in,
                              void* d_out, int out_size) {
    const float* x1 = (const float*)d_in[0];
    const float* x2 = (const float*)d_in[1];
    const float* w1 = (const float*)d_in[2];
    const float* w2 = (const float*)d_in[3];
    float* out = (float*)d_out;

    (void)cudaFuncSetAttribute(attn_kernel,
                               cudaFuncAttributeMaxDynamicSharedMemorySize, ATTN_SMEM);
    (void)cudaFuncSetAttribute(kv_gemm,
                               cudaFuncAttributeMaxDynamicSharedMemorySize, KV_SMEM);

    __half *xh0, *wh0;
    (void)cudaGetSymbolAddress((void**)&xh0, g_xh);
    (void)cudaGetSymbolAddress((void**)&wh0, g_wh);

    split_all<<<(TOT4 + 255) / 256, 256>>>(x1, x2, w1, w2, xh0, wh0);

    dim3 g1(KVN / 128, M_TOT / 128, 2);
    kv_gemm<<<g1, 256, KV_SMEM>>>(0);

    dim3 g2(NSEQ / 128, NB * NHEADS, 2);
    attn_kernel<<<g2, 256, ATTN_SMEM>>>(x1, x2, out);
}